// round 2
// baseline (speedup 1.0000x reference)
#include <cuda_runtime.h>
#include <math.h>

// Problem constants
// B=2, N=8192, DIM=512, H=8, A=256, D=64
// qkv scratch: [16384, 1536]
// big scratch (reused): S2 [16,256,8192] then qa [16,8192,256]  (same size)
// kv, kv2: [16,256,64]

__device__ float g_qkv[16384 * 1536];        // 25165824 floats
__device__ float g_big[16 * 8192 * 256];     // 33554432 floats (S2 then qa)
__device__ float g_kv [16 * 256 * 64];       // 262144
__device__ float g_kv2[16 * 256 * 64];       // 262144
__device__ float g_tsum;

// ---------------------------------------------------------------------------
// init: zero the atomic-accumulated buffers (must be per-call for graph replay)
// ---------------------------------------------------------------------------
__global__ void init_kernel() {
    int i = blockIdx.x * blockDim.x + threadIdx.x;
    if (i == 0) g_tsum = 0.f;
    for (; i < 16 * 256 * 64; i += gridDim.x * blockDim.x) g_kv[i] = 0.f;
}

// ---------------------------------------------------------------------------
// Batched SGEMM: C = alpha * A * op(B)
//   TRANSB=true : B is [N,K] row-major (C = A*B^T)
//   TRANSB=false: B is [K,N] row-major (C = A*B)
// Batch offset for operand X at batch z: (z>>3)*sX1 + (z&7)*sX2
// Split-K: blockIdx.y = kslice*mTiles + mtile; ATOMIC=true accumulates via atomicAdd.
// Tiles: BM=128, BN=64, BK=16, 256 threads, 8x4 per-thread fragments.
// ---------------------------------------------------------------------------
template <bool TRANSB, bool ATOMIC>
__global__ __launch_bounds__(256)
void gemm_kernel(const float* __restrict__ A, int lda, long sA1, long sA2,
                 const float* __restrict__ Bm, int ldb, long sB1, long sB2,
                 float* __restrict__ C, int ldc, long sC1, long sC2,
                 int M, int N, int K, int kSplit, float alpha)
{
    const int BM = 128, BN = 64, BK = 16;
    int z = blockIdx.z;
    const float* Ab = A  + (long)(z >> 3) * sA1 + (long)(z & 7) * sA2;
    const float* Bb = Bm + (long)(z >> 3) * sB1 + (long)(z & 7) * sB2;
    float*       Cb = C  + (long)(z >> 3) * sC1 + (long)(z & 7) * sC2;

    int mTiles = M / BM;
    int mt = blockIdx.y % mTiles;
    int ks = blockIdx.y / mTiles;
    int nt = blockIdx.x;
    int Kc = K / kSplit;
    long kbeg = (long)ks * Kc;

    __shared__ float As[BK][BM];
    __shared__ float Bs[BK][BN];

    int tid  = threadIdx.x;
    int arow = tid >> 2;          // 0..63
    int acol = (tid & 3) << 2;    // 0,4,8,12
    int rowt = tid >> 4;          // 0..15 -> rows rowt*8 .. +7
    int colt = tid & 15;          // cols colt*4 .. +3

    float acc[8][4];
#pragma unroll
    for (int i = 0; i < 8; i++)
#pragma unroll
        for (int j = 0; j < 4; j++) acc[i][j] = 0.f;

    for (int kk = 0; kk < Kc; kk += BK) {
        long k0 = kbeg + kk;
        // --- load A tile [BM x BK], store transposed As[k][m]
        float4 a0 = *(const float4*)(Ab + (long)(mt * BM + arow)      * lda + k0 + acol);
        float4 a1 = *(const float4*)(Ab + (long)(mt * BM + arow + 64) * lda + k0 + acol);
        As[acol + 0][arow] = a0.x; As[acol + 1][arow] = a0.y;
        As[acol + 2][arow] = a0.z; As[acol + 3][arow] = a0.w;
        As[acol + 0][arow + 64] = a1.x; As[acol + 1][arow + 64] = a1.y;
        As[acol + 2][arow + 64] = a1.z; As[acol + 3][arow + 64] = a1.w;
        // --- load B tile
        if (TRANSB) {
            int br = tid >> 2;            // 0..63 (N row)
            int bc = (tid & 3) << 2;      // k quad
            float4 b0 = *(const float4*)(Bb + (long)(nt * BN + br) * ldb + k0 + bc);
            Bs[bc + 0][br] = b0.x; Bs[bc + 1][br] = b0.y;
            Bs[bc + 2][br] = b0.z; Bs[bc + 3][br] = b0.w;
        } else {
            int br = tid >> 4;            // 0..15 (k row)
            int bc = (tid & 15) << 2;     // n quad
            float4 b0 = *(const float4*)(Bb + (k0 + br) * (long)ldb + nt * BN + bc);
            *(float4*)&Bs[br][bc] = b0;
        }
        __syncthreads();
#pragma unroll
        for (int k = 0; k < BK; k++) {
            float4 af0 = *(const float4*)&As[k][rowt * 8];
            float4 af1 = *(const float4*)&As[k][rowt * 8 + 4];
            float4 bf  = *(const float4*)&Bs[k][colt * 4];
            float a[8] = {af0.x, af0.y, af0.z, af0.w, af1.x, af1.y, af1.z, af1.w};
            float b[4] = {bf.x, bf.y, bf.z, bf.w};
#pragma unroll
            for (int i = 0; i < 8; i++)
#pragma unroll
                for (int j = 0; j < 4; j++)
                    acc[i][j] += a[i] * b[j];
        }
        __syncthreads();
    }

#pragma unroll
    for (int i = 0; i < 8; i++) {
        long row = (long)(mt * BM + rowt * 8 + i);
        long base = row * ldc + nt * BN + colt * 4;
        if (ATOMIC) {
#pragma unroll
            for (int j = 0; j < 4; j++)
                atomicAdd(&Cb[base + j], alpha * acc[i][j]);
        } else {
            float4 v = make_float4(alpha * acc[i][0], alpha * acc[i][1],
                                   alpha * acc[i][2], alpha * acc[i][3]);
            *(float4*)&Cb[base] = v;
        }
    }
}

// ---------------------------------------------------------------------------
// Row softmax, row length 8192 (for S2: [4096 rows, 8192]) in-place
// ---------------------------------------------------------------------------
__global__ __launch_bounds__(256)
void softmax_rows8192(float* __restrict__ S)
{
    __shared__ float buf[8192];
    __shared__ float red[256];
    float* row = S + (long)blockIdx.x * 8192;
    int t = threadIdx.x;

    float m = -3.4e38f;
    for (int i = t * 4; i < 8192; i += 1024) {
        float4 v = *(const float4*)(row + i);
        *(float4*)&buf[i] = v;
        m = fmaxf(m, fmaxf(fmaxf(v.x, v.y), fmaxf(v.z, v.w)));
    }
    red[t] = m; __syncthreads();
    for (int s = 128; s > 0; s >>= 1) {
        if (t < s) red[t] = fmaxf(red[t], red[t + s]);
        __syncthreads();
    }
    m = red[0]; __syncthreads();

    float sum = 0.f;
    for (int i = t * 4; i < 8192; i += 1024) {
        float4 v = *(const float4*)&buf[i];
        v.x = expf(v.x - m); v.y = expf(v.y - m);
        v.z = expf(v.z - m); v.w = expf(v.w - m);
        *(float4*)&buf[i] = v;
        sum += v.x + v.y + v.z + v.w;
    }
    red[t] = sum; __syncthreads();
    for (int s = 128; s > 0; s >>= 1) {
        if (t < s) red[t] += red[t + s];
        __syncthreads();
    }
    float inv = 1.f / red[0];

    for (int i = t * 4; i < 8192; i += 1024) {
        float4 v = *(const float4*)&buf[i];
        v.x *= inv; v.y *= inv; v.z *= inv; v.w *= inv;
        *(float4*)(row + i) = v;
    }
}

// ---------------------------------------------------------------------------
// Row softmax, row length 256, one warp per row (for qa: 131072 rows) in-place
// ---------------------------------------------------------------------------
__global__ __launch_bounds__(256)
void softmax_rows256(float* __restrict__ Q)
{
    int warp = threadIdx.x >> 5;
    int lane = threadIdx.x & 31;
    long row = (long)blockIdx.x * 8 + warp;
    float* p = Q + row * 256;

    float4 v0 = *(const float4*)(p + lane * 4);
    float4 v1 = *(const float4*)(p + 128 + lane * 4);
    float m = fmaxf(fmaxf(fmaxf(v0.x, v0.y), fmaxf(v0.z, v0.w)),
                    fmaxf(fmaxf(v1.x, v1.y), fmaxf(v1.z, v1.w)));
#pragma unroll
    for (int o = 16; o > 0; o >>= 1) m = fmaxf(m, __shfl_xor_sync(0xffffffffu, m, o));

    v0.x = expf(v0.x - m); v0.y = expf(v0.y - m); v0.z = expf(v0.z - m); v0.w = expf(v0.w - m);
    v1.x = expf(v1.x - m); v1.y = expf(v1.y - m); v1.z = expf(v1.z - m); v1.w = expf(v1.w - m);
    float s = v0.x + v0.y + v0.z + v0.w + v1.x + v1.y + v1.z + v1.w;
#pragma unroll
    for (int o = 16; o > 0; o >>= 1) s += __shfl_xor_sync(0xffffffffu, s, o);
    float inv = 1.f / s;

    v0.x *= inv; v0.y *= inv; v0.z *= inv; v0.w *= inv;
    v1.x *= inv; v1.y *= inv; v1.z *= inv; v1.w *= inv;
    *(float4*)(p + lane * 4) = v0;
    *(float4*)(p + 128 + lane * 4) = v1;
}

// ---------------------------------------------------------------------------
// Threshold partial sum.
// Reference: kv_c = kv.reshape(b, a, h*d) is a ROW-MAJOR REINTERPRET of the
// [b,h,a,d] buffer, so column index within a 512-row is simply flat%512.
// tsum = sum_i kv_flat[i] * w_thresh[i % 512]; thresh = sigmoid(tsum/512 + b).
// ---------------------------------------------------------------------------
__global__ __launch_bounds__(256)
void thresh_kernel(const float* __restrict__ kv, const float* __restrict__ wth)
{
    __shared__ float red[256];
    float s = 0.f;
    for (long i = blockIdx.x * 256 + threadIdx.x; i < 16L * 256 * 64;
         i += (long)gridDim.x * 256) {
        s += kv[i] * wth[i & 511];
    }
    red[threadIdx.x] = s; __syncthreads();
    for (int st = 128; st > 0; st >>= 1) {
        if (threadIdx.x < st) red[threadIdx.x] += red[threadIdx.x + st];
        __syncthreads();
    }
    if (threadIdx.x == 0) atomicAdd(&g_tsum, red[0]);
}

__device__ __forceinline__ float sigmoidf_(float x) { return 1.f / (1.f + expf(-x)); }

// ---------------------------------------------------------------------------
// kv2 = softmax_d( kv * (sigmoid(kv@w_mask^T+b_mask) > thresh) + sigmoid(kv@w_noise^T+b_noise) )
// one block (64 threads) per row (b,h,a); 4096 rows
// ---------------------------------------------------------------------------
__global__ __launch_bounds__(64)
void kv2_kernel(const float* __restrict__ kv, float* __restrict__ kv2,
                const float* __restrict__ wn, const float* __restrict__ bn,
                const float* __restrict__ wm, const float* __restrict__ bm,
                const float* __restrict__ bth)
{
    long r = blockIdx.x;
    int d = threadIdx.x;
    __shared__ float kr[64];
    __shared__ float tmp[64];

    kr[d] = kv[r * 64 + d];
    __syncthreads();

    float thresh = sigmoidf_(g_tsum * (1.f / 512.f) + bth[0]);

    float sn = bn[d], sm = bm[d];
#pragma unroll 8
    for (int e = 0; e < 64; e++) {
        float ke = kr[e];
        sn += ke * wn[d * 64 + e];
        sm += ke * wm[d * 64 + e];
    }
    float denoise = sigmoidf_(sn);
    float mval    = sigmoidf_(sm);
    float mbin    = (mval > thresh) ? 1.f : 0.f;
    float val     = kr[d] * mbin + denoise;

    tmp[d] = val; __syncthreads();
    float mx = -3.4e38f;
    for (int e = 0; e < 64; e++) mx = fmaxf(mx, tmp[e]);
    __syncthreads();
    float ev = expf(val - mx);
    tmp[d] = ev; __syncthreads();
    float sum = 0.f;
    for (int e = 0; e < 64; e++) sum += tmp[e];
    kv2[r * 64 + d] = ev / sum;
}

// ---------------------------------------------------------------------------
extern "C" void kernel_launch(void* const* d_in, const int* in_sizes, int n_in,
                              void* d_out, int out_size)
{
    const float* x        = (const float*)d_in[0];
    const float* w_qkv    = (const float*)d_in[1];
    const float* agent    = (const float*)d_in[2];
    const float* w_noise  = (const float*)d_in[3];
    const float* b_noise  = (const float*)d_in[4];
    const float* w_mask   = (const float*)d_in[5];
    const float* b_mask   = (const float*)d_in[6];
    const float* w_thresh = (const float*)d_in[7];
    const float* b_thresh = (const float*)d_in[8];
    float* out = (float*)d_out;

    float *qkv, *big, *kv, *kv2;
    cudaGetSymbolAddress((void**)&qkv, g_qkv);
    cudaGetSymbolAddress((void**)&big, g_big);
    cudaGetSymbolAddress((void**)&kv,  g_kv);
    cudaGetSymbolAddress((void**)&kv2, g_kv2);

    init_kernel<<<256, 256>>>();

    // 1) qkv = x @ w_qkv^T : [16384,1536], K=512
    gemm_kernel<true, false><<<dim3(24, 128, 1), 256>>>(
        x, 512, 0, 0,
        w_qkv, 512, 0, 0,
        qkv, 1536, 0, 0,
        16384, 1536, 512, 1, 1.f);

    // 2) S2[z] = agent[h] @ k[b,h]^T : [256,8192], K=64, z=(b*8+h)
    gemm_kernel<true, false><<<dim3(128, 2, 16), 256>>>(
        agent, 64, 0, 16384,
        qkv + 512, 1536, 12582912L, 64,
        big, 8192, 16777216L, 2097152L,
        256, 8192, 64, 1, 1.f);

    // 3) softmax over n (rows of length 8192): 16*256 = 4096 rows
    softmax_rows8192<<<4096, 256>>>(big);

    // 4) kv[z] = S2[z] @ v[b,h] : [256,64], K=8192, split-K=32 with atomicAdd
    gemm_kernel<false, true><<<dim3(1, 64, 16), 256>>>(
        big, 8192, 16777216L, 2097152L,
        qkv + 1024, 1536, 12582912L, 64,
        kv, 64, 131072L, 16384L,
        256, 64, 8192, 32, 1.f);

    // 5) threshold scalar (flat index % 512 pairing per row-major reshape)
    thresh_kernel<<<512, 256>>>(kv, w_thresh);

    // 6) mask/denoise + second softmax -> kv2
    kv2_kernel<<<4096, 64>>>(kv, kv2, w_noise, b_noise, w_mask, b_mask, b_thresh);

    // 7) qa_logits[z] = q[b,h] @ agent[h]^T * 1/8 : [8192,256], K=64
    gemm_kernel<true, false><<<dim3(4, 64, 16), 256>>>(
        qkv, 1536, 12582912L, 64,
        agent, 64, 0, 16384,
        big, 256, 16777216L, 2097152L,
        8192, 256, 64, 1, 0.125f);

    // 8) softmax over a (rows of length 256): 131072 rows, warp per row
    softmax_rows256<<<16384, 256>>>(big);

    // 9) out[b,n,h*64+d] = qa[z] @ kv2[z] : [8192,64], K=256
    gemm_kernel<false, false><<<dim3(1, 64, 16), 256>>>(
        big, 256, 16777216L, 2097152L,
        kv2, 64, 131072L, 16384L,
        out, 512, 4194304L, 64,
        8192, 64, 256, 1, 1.f);
}

// round 6
// speedup vs baseline: 1.4363x; 1.4363x over previous
#include <cuda_runtime.h>
#include <cuda_bf16.h>
#include <math.h>
#include <cstdint>

// Problem constants: B=2, N=8192, DIM=512, H=8, A=256, D=64
__device__ float g_qkv[16384 * 1536];        // qkv scratch
__device__ float g_big[16 * 8192 * 256];     // S2 then qa
__device__ float g_kv [16 * 256 * 64];
__device__ float g_kv2[16 * 256 * 64];
__device__ float g_tsum;
// bf16 hi/lo split buffers for the big GEMM
__device__ __nv_bfloat16 g_xh[16384 * 512];
__device__ __nv_bfloat16 g_xl[16384 * 512];
__device__ __nv_bfloat16 g_wh[1536 * 512];
__device__ __nv_bfloat16 g_wl[1536 * 512];

// ===========================================================================
// PTX helpers (legacy mma path — tcgen05 is not available on compute_103 base)
// ===========================================================================
__device__ __forceinline__ uint32_t smem_to_u32(const void* p) {
    uint32_t a;
    asm("{ .reg .u64 t; cvta.to.shared.u64 t, %1; cvt.u32.u64 %0, t; }" : "=r"(a) : "l"(p));
    return a;
}
#define LDMATRIX_X4(r0, r1, r2, r3, addr) \
    asm volatile("ldmatrix.sync.aligned.m8n8.x4.shared.b16 {%0,%1,%2,%3}, [%4];" \
                 : "=r"(r0), "=r"(r1), "=r"(r2), "=r"(r3) : "r"(addr))
#define MMA_BF16(c, a, b) \
    asm volatile("mma.sync.aligned.m16n8k16.row.col.f32.bf16.bf16.f32 " \
                 "{%0,%1,%2,%3}, {%4,%5,%6,%7}, {%8,%9}, {%0,%1,%2,%3};" \
                 : "+f"((c)[0]), "+f"((c)[1]), "+f"((c)[2]), "+f"((c)[3]) \
                 : "r"((a)[0]), "r"((a)[1]), "r"((a)[2]), "r"((a)[3]), \
                   "r"((b)[0]), "r"((b)[1]))
#define CP_ASYNC16(dst, src) \
    asm volatile("cp.async.cg.shared.global [%0], [%1], 16;" :: "r"(dst), "l"(src))
#define CP_COMMIT() asm volatile("cp.async.commit_group;" ::: "memory")
#define CP_WAIT0()  asm volatile("cp.async.wait_group 0;" ::: "memory")

// ===========================================================================
// bf16 split: hi = bf16(v), lo = bf16(v - hi)
// ===========================================================================
__global__ __launch_bounds__(256)
void split_bf16(const float* __restrict__ in, __nv_bfloat16* __restrict__ hi,
                __nv_bfloat16* __restrict__ lo, long n) {
    for (long i = ((long)blockIdx.x * blockDim.x + threadIdx.x) * 4; i < n;
         i += (long)gridDim.x * blockDim.x * 4) {
        float4 v = *(const float4*)(in + i);
        __nv_bfloat16 h0 = __float2bfloat16_rn(v.x);
        __nv_bfloat16 h1 = __float2bfloat16_rn(v.y);
        __nv_bfloat16 h2 = __float2bfloat16_rn(v.z);
        __nv_bfloat16 h3 = __float2bfloat16_rn(v.w);
        __nv_bfloat162 hh0 = {h0, h1}, hh1 = {h2, h3};
        __nv_bfloat162 ll0 = {__float2bfloat16_rn(v.x - __bfloat162float(h0)),
                              __float2bfloat16_rn(v.y - __bfloat162float(h1))};
        __nv_bfloat162 ll1 = {__float2bfloat16_rn(v.z - __bfloat162float(h2)),
                              __float2bfloat16_rn(v.w - __bfloat162float(h3))};
        *(__nv_bfloat162*)(hi + i)     = hh0;
        *(__nv_bfloat162*)(hi + i + 2) = hh1;
        *(__nv_bfloat162*)(lo + i)     = ll0;
        *(__nv_bfloat162*)(lo + i + 2) = ll1;
    }
}

// ===========================================================================
// K1: C[16384,1536] = X[16384,512] @ W[1536,512]^T via bf16x3 mma.sync.
// CTA tile 128x128, BK=32, 8 warps (2m x 4n), warp tile 64x32.
// SMEM per stage: Ah/Al/Bh/Bl, each 128 rows x 32 bf16, row stride 80 B
// (64 B data + 16 B pad -> conflict-free ldmatrix granules). Stage = 40960 B.
// ===========================================================================
static constexpr int K1_ROWB = 80;
static constexpr int K1_BUF  = 128 * K1_ROWB;        // 10240
static constexpr int K1_STAGE = 4 * K1_BUF;          // 40960
static constexpr int K1_SMEM  = 2 * K1_STAGE;        // 81920

__global__ __launch_bounds__(256)
void k1_mma_kernel(const __nv_bfloat16* __restrict__ xh,
                   const __nv_bfloat16* __restrict__ xl,
                   const __nv_bfloat16* __restrict__ wh,
                   const __nv_bfloat16* __restrict__ wl,
                   float* __restrict__ C)
{
    extern __shared__ char smem[];
    uint32_t sb = smem_to_u32(smem);
    int tid = threadIdx.x;
    int lane = tid & 31, wid = tid >> 5;
    int mw = wid & 1, nw = wid >> 1;          // warp grid 2m x 4n
    int nt = blockIdx.x, mt = blockIdx.y;

    const __nv_bfloat16* srcA_h = xh + (long)(mt * 128) * 512;
    const __nv_bfloat16* srcA_l = xl + (long)(mt * 128) * 512;
    const __nv_bfloat16* srcB_h = wh + (long)(nt * 128) * 512;
    const __nv_bfloat16* srcB_l = wl + (long)(nt * 128) * 512;

    float acc[4][4][4];
#pragma unroll
    for (int i = 0; i < 4; i++)
#pragma unroll
        for (int j = 0; j < 4; j++)
#pragma unroll
            for (int q = 0; q < 4; q++) acc[i][j][q] = 0.f;

    // ldmatrix per-lane address components
    int a_tile = lane >> 3, a_rin = lane & 7;
    // A: tile0 rows+0 kh0, tile1 rows+8 kh0, tile2 rows+0 kh1, tile3 rows+8 kh1
    int a_row = a_rin + (a_tile & 1) * 8;
    int a_kb  = (a_tile >> 1) * 16;
    // B: tile0 n+0 kh0, tile1 n+0 kh1, tile2 n+8 kh0, tile3 n+8 kh1
    int b_row = (a_tile >> 1) * 8 + a_rin;
    int b_kb  = (a_tile & 1) * 16;

    auto issue_loads = [&](int stage, int k0) {
        uint32_t base = sb + stage * K1_STAGE;
#pragma unroll
        for (int j = 0; j < 8; j++) {
            int idx = tid + j * 256;
            int buf = idx >> 9;            // 0..3
            int r   = (idx >> 2) & 127;
            int g   = idx & 3;
            const __nv_bfloat16* src =
                (buf == 0 ? srcA_h : buf == 1 ? srcA_l : buf == 2 ? srcB_h : srcB_l)
                + (long)r * 512 + k0 + g * 8;
            uint32_t dst = base + buf * K1_BUF + r * K1_ROWB + g * 16;
            CP_ASYNC16(dst, src);
        }
    };

    issue_loads(0, 0);
    CP_COMMIT(); CP_WAIT0();
    __syncthreads();

    for (int kc = 0; kc < 16; ++kc) {
        int cur = kc & 1;
        if (kc < 15) { issue_loads(cur ^ 1, (kc + 1) * 32); CP_COMMIT(); }

        uint32_t st = sb + cur * K1_STAGE;
        uint32_t Ah = st,              Al = st + K1_BUF;
        uint32_t Bh = st + 2 * K1_BUF, Bl = st + 3 * K1_BUF;

#pragma unroll
        for (int s = 0; s < 2; ++s) {
            int skb = s * 32;
            uint32_t ah[4][4], al[4][4], bh[4][2], bl[4][2];
#pragma unroll
            for (int mf = 0; mf < 4; mf++) {
                uint32_t addr = Ah + (mw * 64 + mf * 16 + a_row) * K1_ROWB + skb + a_kb;
                LDMATRIX_X4(ah[mf][0], ah[mf][1], ah[mf][2], ah[mf][3], addr);
            }
#pragma unroll
            for (int p = 0; p < 2; p++) {
                uint32_t addr = Bh + (nw * 32 + p * 16 + b_row) * K1_ROWB + skb + b_kb;
                LDMATRIX_X4(bh[p * 2][0], bh[p * 2][1], bh[p * 2 + 1][0], bh[p * 2 + 1][1], addr);
                uint32_t addr2 = Bl + (nw * 32 + p * 16 + b_row) * K1_ROWB + skb + b_kb;
                LDMATRIX_X4(bl[p * 2][0], bl[p * 2][1], bl[p * 2 + 1][0], bl[p * 2 + 1][1], addr2);
            }
#pragma unroll
            for (int mf = 0; mf < 4; mf++)
#pragma unroll
                for (int nf = 0; nf < 4; nf++) MMA_BF16(acc[mf][nf], ah[mf], bh[nf]);
#pragma unroll
            for (int mf = 0; mf < 4; mf++)
#pragma unroll
                for (int nf = 0; nf < 4; nf++) MMA_BF16(acc[mf][nf], ah[mf], bl[nf]);
#pragma unroll
            for (int mf = 0; mf < 4; mf++) {
                uint32_t addr = Al + (mw * 64 + mf * 16 + a_row) * K1_ROWB + skb + a_kb;
                LDMATRIX_X4(al[mf][0], al[mf][1], al[mf][2], al[mf][3], addr);
            }
#pragma unroll
            for (int mf = 0; mf < 4; mf++)
#pragma unroll
                for (int nf = 0; nf < 4; nf++) MMA_BF16(acc[mf][nf], al[mf], bh[nf]);
        }

        if (kc < 15) CP_WAIT0();
        __syncthreads();
    }

    // Epilogue: acc frag (m16n8): c0,c1 at row lane>>2, cols (lane&3)*2..+1; c2,c3 at row+8
    int rbase = mt * 128 + mw * 64 + (lane >> 2);
    int cbase = nt * 128 + nw * 32 + (lane & 3) * 2;
#pragma unroll
    for (int mf = 0; mf < 4; mf++)
#pragma unroll
        for (int nf = 0; nf < 4; nf++) {
            long r0 = rbase + mf * 16;
            long cc = cbase + nf * 8;
            *(float2*)(C + r0 * 1536 + cc)       = make_float2(acc[mf][nf][0], acc[mf][nf][1]);
            *(float2*)(C + (r0 + 8) * 1536 + cc) = make_float2(acc[mf][nf][2], acc[mf][nf][3]);
        }
}

// ===========================================================================
// init: zero the atomic-accumulated buffers
// ===========================================================================
__global__ void init_kernel() {
    int i = blockIdx.x * blockDim.x + threadIdx.x;
    if (i == 0) g_tsum = 0.f;
    for (; i < 16 * 256 * 64; i += gridDim.x * blockDim.x) g_kv[i] = 0.f;
}

// ===========================================================================
// Batched SGEMM (SIMT) — small GEMM stages
// ===========================================================================
template <bool TRANSB, bool ATOMIC>
__global__ __launch_bounds__(256)
void gemm_kernel(const float* __restrict__ A, int lda, long sA1, long sA2,
                 const float* __restrict__ Bm, int ldb, long sB1, long sB2,
                 float* __restrict__ C, int ldc, long sC1, long sC2,
                 int M, int N, int K, int kSplit, float alpha)
{
    const int BM = 128, BN = 64, BK = 16;
    int z = blockIdx.z;
    const float* Ab = A  + (long)(z >> 3) * sA1 + (long)(z & 7) * sA2;
    const float* Bb = Bm + (long)(z >> 3) * sB1 + (long)(z & 7) * sB2;
    float*       Cb = C  + (long)(z >> 3) * sC1 + (long)(z & 7) * sC2;

    int mTiles = M / BM;
    int mt = blockIdx.y % mTiles;
    int ks = blockIdx.y / mTiles;
    int nt = blockIdx.x;
    int Kc = K / kSplit;
    long kbeg = (long)ks * Kc;

    __shared__ float As[BK][BM];
    __shared__ float Bs[BK][BN];

    int tid  = threadIdx.x;
    int arow = tid >> 2;
    int acol = (tid & 3) << 2;
    int rowt = tid >> 4;
    int colt = tid & 15;

    float acc[8][4];
#pragma unroll
    for (int i = 0; i < 8; i++)
#pragma unroll
        for (int j = 0; j < 4; j++) acc[i][j] = 0.f;

    for (int kk = 0; kk < Kc; kk += BK) {
        long k0 = kbeg + kk;
        float4 a0 = *(const float4*)(Ab + (long)(mt * BM + arow)      * lda + k0 + acol);
        float4 a1 = *(const float4*)(Ab + (long)(mt * BM + arow + 64) * lda + k0 + acol);
        As[acol + 0][arow] = a0.x; As[acol + 1][arow] = a0.y;
        As[acol + 2][arow] = a0.z; As[acol + 3][arow] = a0.w;
        As[acol + 0][arow + 64] = a1.x; As[acol + 1][arow + 64] = a1.y;
        As[acol + 2][arow + 64] = a1.z; As[acol + 3][arow + 64] = a1.w;
        if (TRANSB) {
            int br = tid >> 2;
            int bc = (tid & 3) << 2;
            float4 b0 = *(const float4*)(Bb + (long)(nt * BN + br) * ldb + k0 + bc);
            Bs[bc + 0][br] = b0.x; Bs[bc + 1][br] = b0.y;
            Bs[bc + 2][br] = b0.z; Bs[bc + 3][br] = b0.w;
        } else {
            int br = tid >> 4;
            int bc = (tid & 15) << 2;
            float4 b0 = *(const float4*)(Bb + (k0 + br) * (long)ldb + nt * BN + bc);
            *(float4*)&Bs[br][bc] = b0;
        }
        __syncthreads();
#pragma unroll
        for (int k = 0; k < BK; k++) {
            float4 af0 = *(const float4*)&As[k][rowt * 8];
            float4 af1 = *(const float4*)&As[k][rowt * 8 + 4];
            float4 bf  = *(const float4*)&Bs[k][colt * 4];
            float a[8] = {af0.x, af0.y, af0.z, af0.w, af1.x, af1.y, af1.z, af1.w};
            float b[4] = {bf.x, bf.y, bf.z, bf.w};
#pragma unroll
            for (int i = 0; i < 8; i++)
#pragma unroll
                for (int j = 0; j < 4; j++)
                    acc[i][j] += a[i] * b[j];
        }
        __syncthreads();
    }

#pragma unroll
    for (int i = 0; i < 8; i++) {
        long r = (long)(mt * BM + rowt * 8 + i);
        long base = r * ldc + nt * BN + colt * 4;
        if (ATOMIC) {
#pragma unroll
            for (int j = 0; j < 4; j++)
                atomicAdd(&Cb[base + j], alpha * acc[i][j]);
        } else {
            float4 v = make_float4(alpha * acc[i][0], alpha * acc[i][1],
                                   alpha * acc[i][2], alpha * acc[i][3]);
            *(float4*)&Cb[base] = v;
        }
    }
}

// ===========================================================================
// Softmaxes & elementwise stages
// ===========================================================================
__global__ __launch_bounds__(256)
void softmax_rows8192(float* __restrict__ S)
{
    __shared__ float buf[8192];
    __shared__ float red[256];
    float* row = S + (long)blockIdx.x * 8192;
    int t = threadIdx.x;

    float m = -3.4e38f;
    for (int i = t * 4; i < 8192; i += 1024) {
        float4 v = *(const float4*)(row + i);
        *(float4*)&buf[i] = v;
        m = fmaxf(m, fmaxf(fmaxf(v.x, v.y), fmaxf(v.z, v.w)));
    }
    red[t] = m; __syncthreads();
    for (int s = 128; s > 0; s >>= 1) {
        if (t < s) red[t] = fmaxf(red[t], red[t + s]);
        __syncthreads();
    }
    m = red[0]; __syncthreads();

    float sum = 0.f;
    for (int i = t * 4; i < 8192; i += 1024) {
        float4 v = *(const float4*)&buf[i];
        v.x = expf(v.x - m); v.y = expf(v.y - m);
        v.z = expf(v.z - m); v.w = expf(v.w - m);
        *(float4*)&buf[i] = v;
        sum += v.x + v.y + v.z + v.w;
    }
    red[t] = sum; __syncthreads();
    for (int s = 128; s > 0; s >>= 1) {
        if (t < s) red[t] += red[t + s];
        __syncthreads();
    }
    float inv = 1.f / red[0];

    for (int i = t * 4; i < 8192; i += 1024) {
        float4 v = *(const float4*)&buf[i];
        v.x *= inv; v.y *= inv; v.z *= inv; v.w *= inv;
        *(float4*)(row + i) = v;
    }
}

__global__ __launch_bounds__(256)
void softmax_rows256(float* __restrict__ Q)
{
    int warp = threadIdx.x >> 5;
    int lane = threadIdx.x & 31;
    long row = (long)blockIdx.x * 8 + warp;
    float* p = Q + row * 256;

    float4 v0 = *(const float4*)(p + lane * 4);
    float4 v1 = *(const float4*)(p + 128 + lane * 4);
    float m = fmaxf(fmaxf(fmaxf(v0.x, v0.y), fmaxf(v0.z, v0.w)),
                    fmaxf(fmaxf(v1.x, v1.y), fmaxf(v1.z, v1.w)));
#pragma unroll
    for (int o = 16; o > 0; o >>= 1) m = fmaxf(m, __shfl_xor_sync(0xffffffffu, m, o));

    v0.x = expf(v0.x - m); v0.y = expf(v0.y - m); v0.z = expf(v0.z - m); v0.w = expf(v0.w - m);
    v1.x = expf(v1.x - m); v1.y = expf(v1.y - m); v1.z = expf(v1.z - m); v1.w = expf(v1.w - m);
    float s = v0.x + v0.y + v0.z + v0.w + v1.x + v1.y + v1.z + v1.w;
#pragma unroll
    for (int o = 16; o > 0; o >>= 1) s += __shfl_xor_sync(0xffffffffu, s, o);
    float inv = 1.f / s;

    v0.x *= inv; v0.y *= inv; v0.z *= inv; v0.w *= inv;
    v1.x *= inv; v1.y *= inv; v1.z *= inv; v1.w *= inv;
    *(float4*)(p + lane * 4) = v0;
    *(float4*)(p + 128 + lane * 4) = v1;
}

// thresh: tsum = sum_i kv_flat[i] * w_thresh[i % 512]  (row-major reshape)
__global__ __launch_bounds__(256)
void thresh_kernel(const float* __restrict__ kv, const float* __restrict__ wth)
{
    __shared__ float red[256];
    float s = 0.f;
    for (long i = blockIdx.x * 256 + threadIdx.x; i < 16L * 256 * 64;
         i += (long)gridDim.x * 256) {
        s += kv[i] * wth[i & 511];
    }
    red[threadIdx.x] = s; __syncthreads();
    for (int st = 128; st > 0; st >>= 1) {
        if (threadIdx.x < st) red[threadIdx.x] += red[threadIdx.x + st];
        __syncthreads();
    }
    if (threadIdx.x == 0) atomicAdd(&g_tsum, red[0]);
}

__device__ __forceinline__ float sigmoidf_(float x) { return 1.f / (1.f + expf(-x)); }

__global__ __launch_bounds__(64)
void kv2_kernel(const float* __restrict__ kv, float* __restrict__ kv2,
                const float* __restrict__ wn, const float* __restrict__ bn,
                const float* __restrict__ wm, const float* __restrict__ bm,
                const float* __restrict__ bth)
{
    long r = blockIdx.x;
    int d = threadIdx.x;
    __shared__ float kr[64];
    __shared__ float tmp[64];

    kr[d] = kv[r * 64 + d];
    __syncthreads();

    float thresh = sigmoidf_(g_tsum * (1.f / 512.f) + bth[0]);

    float sn = bn[d], sm = bm[d];
#pragma unroll 8
    for (int e = 0; e < 64; e++) {
        float ke = kr[e];
        sn += ke * wn[d * 64 + e];
        sm += ke * wm[d * 64 + e];
    }
    float denoise = sigmoidf_(sn);
    float mval    = sigmoidf_(sm);
    float mbin    = (mval > thresh) ? 1.f : 0.f;
    float val     = kr[d] * mbin + denoise;

    tmp[d] = val; __syncthreads();
    float mx = -3.4e38f;
    for (int e = 0; e < 64; e++) mx = fmaxf(mx, tmp[e]);
    __syncthreads();
    float ev = expf(val - mx);
    tmp[d] = ev; __syncthreads();
    float sum = 0.f;
    for (int e = 0; e < 64; e++) sum += tmp[e];
    kv2[r * 64 + d] = ev / sum;
}

// ===========================================================================
extern "C" void kernel_launch(void* const* d_in, const int* in_sizes, int n_in,
                              void* d_out, int out_size)
{
    const float* x        = (const float*)d_in[0];
    const float* w_qkv    = (const float*)d_in[1];
    const float* agent    = (const float*)d_in[2];
    const float* w_noise  = (const float*)d_in[3];
    const float* b_noise  = (const float*)d_in[4];
    const float* w_mask   = (const float*)d_in[5];
    const float* b_mask   = (const float*)d_in[6];
    const float* w_thresh = (const float*)d_in[7];
    const float* b_thresh = (const float*)d_in[8];
    float* out = (float*)d_out;

    float *qkv, *big, *kv, *kv2;
    __nv_bfloat16 *xh, *xl, *wh, *wl;
    cudaGetSymbolAddress((void**)&qkv, g_qkv);
    cudaGetSymbolAddress((void**)&big, g_big);
    cudaGetSymbolAddress((void**)&kv,  g_kv);
    cudaGetSymbolAddress((void**)&kv2, g_kv2);
    cudaGetSymbolAddress((void**)&xh,  g_xh);
    cudaGetSymbolAddress((void**)&xl,  g_xl);
    cudaGetSymbolAddress((void**)&wh,  g_wh);
    cudaGetSymbolAddress((void**)&wl,  g_wl);

    cudaFuncSetAttribute(k1_mma_kernel,
                         cudaFuncAttributeMaxDynamicSharedMemorySize, K1_SMEM);

    init_kernel<<<256, 256>>>();

    // 0) bf16 hi/lo split of x and w_qkv
    split_bf16<<<1024, 256>>>(x, xh, xl, 16384L * 512);
    split_bf16<<<256, 256>>>(w_qkv, wh, wl, 1536L * 512);

    // 1) qkv = x @ w_qkv^T via bf16x3 mma.sync : [16384,1536], K=512
    k1_mma_kernel<<<dim3(12, 128), 256, K1_SMEM>>>(xh, xl, wh, wl, qkv);

    // 2) S2[z] = agent[h] @ k[b,h]^T : [256,8192], K=64
    gemm_kernel<true, false><<<dim3(128, 2, 16), 256>>>(
        agent, 64, 0, 16384,
        qkv + 512, 1536, 12582912L, 64,
        big, 8192, 16777216L, 2097152L,
        256, 8192, 64, 1, 1.f);

    // 3) softmax over n
    softmax_rows8192<<<4096, 256>>>(big);

    // 4) kv[z] = S2[z] @ v[b,h] : [256,64], K=8192, split-K=32
    gemm_kernel<false, true><<<dim3(1, 64, 16), 256>>>(
        big, 8192, 16777216L, 2097152L,
        qkv + 1024, 1536, 12582912L, 64,
        kv, 64, 131072L, 16384L,
        256, 64, 8192, 32, 1.f);

    // 5) threshold scalar
    thresh_kernel<<<512, 256>>>(kv, w_thresh);

    // 6) mask/denoise + second softmax -> kv2
    kv2_kernel<<<4096, 64>>>(kv, kv2, w_noise, b_noise, w_mask, b_mask, b_thresh);

    // 7) qa_logits[z] = q[b,h] @ agent[h]^T * 1/8 : [8192,256], K=64
    gemm_kernel<true, false><<<dim3(4, 64, 16), 256>>>(
        qkv, 1536, 12582912L, 64,
        agent, 64, 0, 16384,
        big, 256, 16777216L, 2097152L,
        8192, 256, 64, 1, 0.125f);

    // 8) softmax over a
    softmax_rows256<<<16384, 256>>>(big);

    // 9) out = qa[z] @ kv2[z] : [8192,64], K=256
    gemm_kernel<false, false><<<dim3(1, 64, 16), 256>>>(
        big, 256, 16777216L, 2097152L,
        kv2, 64, 131072L, 16384L,
        out, 512, 4194304L, 64,
        8192, 64, 256, 1, 1.f);
}

// round 9
// speedup vs baseline: 1.4396x; 1.0023x over previous
#include <cuda_runtime.h>
#include <cuda_bf16.h>
#include <math.h>
#include <cstdint>

// Problem constants: B=2, N=8192, DIM=512, H=8, A=256, D=64
__device__ float g_qkv[16384 * 1536];        // qkv scratch
__device__ float g_big[16 * 8192 * 256];     // S2 then qa
__device__ float g_kv [16 * 256 * 64];
__device__ float g_kv2[16 * 256 * 64];
__device__ float g_tsum;
// bf16 hi/lo split buffers for the big GEMM
__device__ __nv_bfloat16 g_xh[16384 * 512];
__device__ __nv_bfloat16 g_xl[16384 * 512];
__device__ __nv_bfloat16 g_wh[1536 * 512];
__device__ __nv_bfloat16 g_wl[1536 * 512];

// ===========================================================================
// PTX helpers (legacy mma path — tcgen05 is not available on compute_103 base)
// ===========================================================================
__device__ __forceinline__ uint32_t smem_to_u32(const void* p) {
    uint32_t a;
    asm("{ .reg .u64 t; cvta.to.shared.u64 t, %1; cvt.u32.u64 %0, t; }" : "=r"(a) : "l"(p));
    return a;
}
#define LDMATRIX_X4(r0, r1, r2, r3, addr) \
    asm volatile("ldmatrix.sync.aligned.m8n8.x4.shared.b16 {%0,%1,%2,%3}, [%4];" \
                 : "=r"(r0), "=r"(r1), "=r"(r2), "=r"(r3) : "r"(addr))
#define MMA_BF16(c, a, b) \
    asm volatile("mma.sync.aligned.m16n8k16.row.col.f32.bf16.bf16.f32 " \
                 "{%0,%1,%2,%3}, {%4,%5,%6,%7}, {%8,%9}, {%0,%1,%2,%3};" \
                 : "+f"((c)[0]), "+f"((c)[1]), "+f"((c)[2]), "+f"((c)[3]) \
                 : "r"((a)[0]), "r"((a)[1]), "r"((a)[2]), "r"((a)[3]), \
                   "r"((b)[0]), "r"((b)[1]))
#define CP_ASYNC16(dst, src) \
    asm volatile("cp.async.cg.shared.global [%0], [%1], 16;" :: "r"(dst), "l"(src))
#define CP_COMMIT() asm volatile("cp.async.commit_group;" ::: "memory")
#define CP_WAIT0()  asm volatile("cp.async.wait_group 0;" ::: "memory")

// ===========================================================================
// bf16 split: hi = bf16(v), lo = bf16(v - hi)
// ===========================================================================
__global__ __launch_bounds__(256)
void split_bf16(const float* __restrict__ in, __nv_bfloat16* __restrict__ hi,
                __nv_bfloat16* __restrict__ lo, long n) {
    for (long i = ((long)blockIdx.x * blockDim.x + threadIdx.x) * 4; i < n;
         i += (long)gridDim.x * blockDim.x * 4) {
        float4 v = *(const float4*)(in + i);
        __nv_bfloat16 h0 = __float2bfloat16_rn(v.x);
        __nv_bfloat16 h1 = __float2bfloat16_rn(v.y);
        __nv_bfloat16 h2 = __float2bfloat16_rn(v.z);
        __nv_bfloat16 h3 = __float2bfloat16_rn(v.w);
        __nv_bfloat162 hh0 = {h0, h1}, hh1 = {h2, h3};
        __nv_bfloat162 ll0 = {__float2bfloat16_rn(v.x - __bfloat162float(h0)),
                              __float2bfloat16_rn(v.y - __bfloat162float(h1))};
        __nv_bfloat162 ll1 = {__float2bfloat16_rn(v.z - __bfloat162float(h2)),
                              __float2bfloat16_rn(v.w - __bfloat162float(h3))};
        *(__nv_bfloat162*)(hi + i)     = hh0;
        *(__nv_bfloat162*)(hi + i + 2) = hh1;
        *(__nv_bfloat162*)(lo + i)     = ll0;
        *(__nv_bfloat162*)(lo + i + 2) = ll1;
    }
}

// ===========================================================================
// K1: C[16384,1536] = X[16384,512] @ W[1536,512]^T via bf16x3 mma.sync.
// CTA tile 128x128, BK=32, 8 warps (2m x 4n), warp tile 64x32.
// SMEM per stage: Ah/Al/Bh/Bl, each 128 rows x 32 bf16, row stride 80 B
// (64 B data + 16 B pad -> conflict-free ldmatrix granules). Stage = 40960 B.
// ===========================================================================
static constexpr int K1_ROWB = 80;
static constexpr int K1_BUF  = 128 * K1_ROWB;        // 10240
static constexpr int K1_STAGE = 4 * K1_BUF;          // 40960
static constexpr int K1_SMEM  = 2 * K1_STAGE;        // 81920

__global__ __launch_bounds__(256)
void k1_mma_kernel(const __nv_bfloat16* __restrict__ xh,
                   const __nv_bfloat16* __restrict__ xl,
                   const __nv_bfloat16* __restrict__ wh,
                   const __nv_bfloat16* __restrict__ wl,
                   float* __restrict__ C)
{
    extern __shared__ char smem[];
    uint32_t sb = smem_to_u32(smem);
    int tid = threadIdx.x;
    int lane = tid & 31, wid = tid >> 5;
    int mw = wid & 1, nw = wid >> 1;          // warp grid 2m x 4n
    int nt = blockIdx.x, mt = blockIdx.y;

    const __nv_bfloat16* srcA_h = xh + (long)(mt * 128) * 512;
    const __nv_bfloat16* srcA_l = xl + (long)(mt * 128) * 512;
    const __nv_bfloat16* srcB_h = wh + (long)(nt * 128) * 512;
    const __nv_bfloat16* srcB_l = wl + (long)(nt * 128) * 512;

    float acc[4][4][4];
#pragma unroll
    for (int i = 0; i < 4; i++)
#pragma unroll
        for (int j = 0; j < 4; j++)
#pragma unroll
            for (int q = 0; q < 4; q++) acc[i][j][q] = 0.f;

    // ldmatrix per-lane address components
    int a_tile = lane >> 3, a_rin = lane & 7;
    // A: tile0 rows+0 kh0, tile1 rows+8 kh0, tile2 rows+0 kh1, tile3 rows+8 kh1
    int a_row = a_rin + (a_tile & 1) * 8;
    int a_kb  = (a_tile >> 1) * 16;
    // B: tile0 n+0 kh0, tile1 n+0 kh1, tile2 n+8 kh0, tile3 n+8 kh1
    int b_row = (a_tile >> 1) * 8 + a_rin;
    int b_kb  = (a_tile & 1) * 16;

    auto issue_loads = [&](int stage, int k0) {
        uint32_t base = sb + stage * K1_STAGE;
#pragma unroll
        for (int j = 0; j < 8; j++) {
            int idx = tid + j * 256;
            int buf = idx >> 9;            // 0..3
            int r   = (idx >> 2) & 127;
            int g   = idx & 3;
            const __nv_bfloat16* src =
                (buf == 0 ? srcA_h : buf == 1 ? srcA_l : buf == 2 ? srcB_h : srcB_l)
                + (long)r * 512 + k0 + g * 8;
            uint32_t dst = base + buf * K1_BUF + r * K1_ROWB + g * 16;
            CP_ASYNC16(dst, src);
        }
    };

    issue_loads(0, 0);
    CP_COMMIT(); CP_WAIT0();
    __syncthreads();

    for (int kc = 0; kc < 16; ++kc) {
        int cur = kc & 1;
        if (kc < 15) { issue_loads(cur ^ 1, (kc + 1) * 32); CP_COMMIT(); }

        uint32_t st = sb + cur * K1_STAGE;
        uint32_t Ah = st,              Al = st + K1_BUF;
        uint32_t Bh = st + 2 * K1_BUF, Bl = st + 3 * K1_BUF;

#pragma unroll
        for (int s = 0; s < 2; ++s) {
            int skb = s * 32;
            uint32_t ah[4][4], al[4][4], bh[4][2], bl[4][2];
#pragma unroll
            for (int mf = 0; mf < 4; mf++) {
                uint32_t addr = Ah + (mw * 64 + mf * 16 + a_row) * K1_ROWB + skb + a_kb;
                LDMATRIX_X4(ah[mf][0], ah[mf][1], ah[mf][2], ah[mf][3], addr);
            }
#pragma unroll
            for (int p = 0; p < 2; p++) {
                uint32_t addr = Bh + (nw * 32 + p * 16 + b_row) * K1_ROWB + skb + b_kb;
                LDMATRIX_X4(bh[p * 2][0], bh[p * 2][1], bh[p * 2 + 1][0], bh[p * 2 + 1][1], addr);
                uint32_t addr2 = Bl + (nw * 32 + p * 16 + b_row) * K1_ROWB + skb + b_kb;
                LDMATRIX_X4(bl[p * 2][0], bl[p * 2][1], bl[p * 2 + 1][0], bl[p * 2 + 1][1], addr2);
            }
#pragma unroll
            for (int mf = 0; mf < 4; mf++)
#pragma unroll
                for (int nf = 0; nf < 4; nf++) MMA_BF16(acc[mf][nf], ah[mf], bh[nf]);
#pragma unroll
            for (int mf = 0; mf < 4; mf++)
#pragma unroll
                for (int nf = 0; nf < 4; nf++) MMA_BF16(acc[mf][nf], ah[mf], bl[nf]);
#pragma unroll
            for (int mf = 0; mf < 4; mf++) {
                uint32_t addr = Al + (mw * 64 + mf * 16 + a_row) * K1_ROWB + skb + a_kb;
                LDMATRIX_X4(al[mf][0], al[mf][1], al[mf][2], al[mf][3], addr);
            }
#pragma unroll
            for (int mf = 0; mf < 4; mf++)
#pragma unroll
                for (int nf = 0; nf < 4; nf++) MMA_BF16(acc[mf][nf], al[mf], bh[nf]);
        }

        if (kc < 15) CP_WAIT0();
        __syncthreads();
    }

    // Epilogue: acc frag (m16n8): c0,c1 at row lane>>2, cols (lane&3)*2..+1; c2,c3 at row+8
    int rbase = mt * 128 + mw * 64 + (lane >> 2);
    int cbase = nt * 128 + nw * 32 + (lane & 3) * 2;
#pragma unroll
    for (int mf = 0; mf < 4; mf++)
#pragma unroll
        for (int nf = 0; nf < 4; nf++) {
            long r0 = rbase + mf * 16;
            long cc = cbase + nf * 8;
            *(float2*)(C + r0 * 1536 + cc)       = make_float2(acc[mf][nf][0], acc[mf][nf][1]);
            *(float2*)(C + (r0 + 8) * 1536 + cc) = make_float2(acc[mf][nf][2], acc[mf][nf][3]);
        }
}

// ===========================================================================
// init: zero the atomic-accumulated buffers
// ===========================================================================
__global__ void init_kernel() {
    int i = blockIdx.x * blockDim.x + threadIdx.x;
    if (i == 0) g_tsum = 0.f;
    for (; i < 16 * 256 * 64; i += gridDim.x * blockDim.x) g_kv[i] = 0.f;
}

// ===========================================================================
// Batched SGEMM (SIMT) — small GEMM stages
// ===========================================================================
template <bool TRANSB, bool ATOMIC>
__global__ __launch_bounds__(256)
void gemm_kernel(const float* __restrict__ A, int lda, long sA1, long sA2,
                 const float* __restrict__ Bm, int ldb, long sB1, long sB2,
                 float* __restrict__ C, int ldc, long sC1, long sC2,
                 int M, int N, int K, int kSplit, float alpha)
{
    const int BM = 128, BN = 64, BK = 16;
    int z = blockIdx.z;
    const float* Ab = A  + (long)(z >> 3) * sA1 + (long)(z & 7) * sA2;
    const float* Bb = Bm + (long)(z >> 3) * sB1 + (long)(z & 7) * sB2;
    float*       Cb = C  + (long)(z >> 3) * sC1 + (long)(z & 7) * sC2;

    int mTiles = M / BM;
    int mt = blockIdx.y % mTiles;
    int ks = blockIdx.y / mTiles;
    int nt = blockIdx.x;
    int Kc = K / kSplit;
    long kbeg = (long)ks * Kc;

    __shared__ float As[BK][BM];
    __shared__ float Bs[BK][BN];

    int tid  = threadIdx.x;
    int arow = tid >> 2;
    int acol = (tid & 3) << 2;
    int rowt = tid >> 4;
    int colt = tid & 15;

    float acc[8][4];
#pragma unroll
    for (int i = 0; i < 8; i++)
#pragma unroll
        for (int j = 0; j < 4; j++) acc[i][j] = 0.f;

    for (int kk = 0; kk < Kc; kk += BK) {
        long k0 = kbeg + kk;
        float4 a0 = *(const float4*)(Ab + (long)(mt * BM + arow)      * lda + k0 + acol);
        float4 a1 = *(const float4*)(Ab + (long)(mt * BM + arow + 64) * lda + k0 + acol);
        As[acol + 0][arow] = a0.x; As[acol + 1][arow] = a0.y;
        As[acol + 2][arow] = a0.z; As[acol + 3][arow] = a0.w;
        As[acol + 0][arow + 64] = a1.x; As[acol + 1][arow + 64] = a1.y;
        As[acol + 2][arow + 64] = a1.z; As[acol + 3][arow + 64] = a1.w;
        if (TRANSB) {
            int br = tid >> 2;
            int bc = (tid & 3) << 2;
            float4 b0 = *(const float4*)(Bb + (long)(nt * BN + br) * ldb + k0 + bc);
            Bs[bc + 0][br] = b0.x; Bs[bc + 1][br] = b0.y;
            Bs[bc + 2][br] = b0.z; Bs[bc + 3][br] = b0.w;
        } else {
            int br = tid >> 4;
            int bc = (tid & 15) << 2;
            float4 b0 = *(const float4*)(Bb + (k0 + br) * (long)ldb + nt * BN + bc);
            *(float4*)&Bs[br][bc] = b0;
        }
        __syncthreads();
#pragma unroll
        for (int k = 0; k < BK; k++) {
            float4 af0 = *(const float4*)&As[k][rowt * 8];
            float4 af1 = *(const float4*)&As[k][rowt * 8 + 4];
            float4 bf  = *(const float4*)&Bs[k][colt * 4];
            float a[8] = {af0.x, af0.y, af0.z, af0.w, af1.x, af1.y, af1.z, af1.w};
            float b[4] = {bf.x, bf.y, bf.z, bf.w};
#pragma unroll
            for (int i = 0; i < 8; i++)
#pragma unroll
                for (int j = 0; j < 4; j++)
                    acc[i][j] += a[i] * b[j];
        }
        __syncthreads();
    }

#pragma unroll
    for (int i = 0; i < 8; i++) {
        long r = (long)(mt * BM + rowt * 8 + i);
        long base = r * ldc + nt * BN + colt * 4;
        if (ATOMIC) {
#pragma unroll
            for (int j = 0; j < 4; j++)
                atomicAdd(&Cb[base + j], alpha * acc[i][j]);
        } else {
            float4 v = make_float4(alpha * acc[i][0], alpha * acc[i][1],
                                   alpha * acc[i][2], alpha * acc[i][3]);
            *(float4*)&Cb[base] = v;
        }
    }
}

// ===========================================================================
// Softmaxes & elementwise stages
// ===========================================================================
__global__ __launch_bounds__(256)
void softmax_rows8192(float* __restrict__ S)
{
    __shared__ float buf[8192];
    __shared__ float red[256];
    float* row = S + (long)blockIdx.x * 8192;
    int t = threadIdx.x;

    float m = -3.4e38f;
    for (int i = t * 4; i < 8192; i += 1024) {
        float4 v = *(const float4*)(row + i);
        *(float4*)&buf[i] = v;
        m = fmaxf(m, fmaxf(fmaxf(v.x, v.y), fmaxf(v.z, v.w)));
    }
    red[t] = m; __syncthreads();
    for (int s = 128; s > 0; s >>= 1) {
        if (t < s) red[t] = fmaxf(red[t], red[t + s]);
        __syncthreads();
    }
    m = red[0]; __syncthreads();

    float sum = 0.f;
    for (int i = t * 4; i < 8192; i += 1024) {
        float4 v = *(const float4*)&buf[i];
        v.x = expf(v.x - m); v.y = expf(v.y - m);
        v.z = expf(v.z - m); v.w = expf(v.w - m);
        *(float4*)&buf[i] = v;
        sum += v.x + v.y + v.z + v.w;
    }
    red[t] = sum; __syncthreads();
    for (int s = 128; s > 0; s >>= 1) {
        if (t < s) red[t] += red[t + s];
        __syncthreads();
    }
    float inv = 1.f / red[0];

    for (int i = t * 4; i < 8192; i += 1024) {
        float4 v = *(const float4*)&buf[i];
        v.x *= inv; v.y *= inv; v.z *= inv; v.w *= inv;
        *(float4*)(row + i) = v;
    }
}

__global__ __launch_bounds__(256)
void softmax_rows256(float* __restrict__ Q)
{
    int warp = threadIdx.x >> 5;
    int lane = threadIdx.x & 31;
    long row = (long)blockIdx.x * 8 + warp;
    float* p = Q + row * 256;

    float4 v0 = *(const float4*)(p + lane * 4);
    float4 v1 = *(const float4*)(p + 128 + lane * 4);
    float m = fmaxf(fmaxf(fmaxf(v0.x, v0.y), fmaxf(v0.z, v0.w)),
                    fmaxf(fmaxf(v1.x, v1.y), fmaxf(v1.z, v1.w)));
#pragma unroll
    for (int o = 16; o > 0; o >>= 1) m = fmaxf(m, __shfl_xor_sync(0xffffffffu, m, o));

    v0.x = expf(v0.x - m); v0.y = expf(v0.y - m); v0.z = expf(v0.z - m); v0.w = expf(v0.w - m);
    v1.x = expf(v1.x - m); v1.y = expf(v1.y - m); v1.z = expf(v1.z - m); v1.w = expf(v1.w - m);
    float s = v0.x + v0.y + v0.z + v0.w + v1.x + v1.y + v1.z + v1.w;
#pragma unroll
    for (int o = 16; o > 0; o >>= 1) s += __shfl_xor_sync(0xffffffffu, s, o);
    float inv = 1.f / s;

    v0.x *= inv; v0.y *= inv; v0.z *= inv; v0.w *= inv;
    v1.x *= inv; v1.y *= inv; v1.z *= inv; v1.w *= inv;
    *(float4*)(p + lane * 4) = v0;
    *(float4*)(p + 128 + lane * 4) = v1;
}

// thresh: tsum = sum_i kv_flat[i] * w_thresh[i % 512]  (row-major reshape)
__global__ __launch_bounds__(256)
void thresh_kernel(const float* __restrict__ kv, const float* __restrict__ wth)
{
    __shared__ float red[256];
    float s = 0.f;
    for (long i = blockIdx.x * 256 + threadIdx.x; i < 16L * 256 * 64;
         i += (long)gridDim.x * 256) {
        s += kv[i] * wth[i & 511];
    }
    red[threadIdx.x] = s; __syncthreads();
    for (int st = 128; st > 0; st >>= 1) {
        if (threadIdx.x < st) red[threadIdx.x] += red[threadIdx.x + st];
        __syncthreads();
    }
    if (threadIdx.x == 0) atomicAdd(&g_tsum, red[0]);
}

__device__ __forceinline__ float sigmoidf_(float x) { return 1.f / (1.f + expf(-x)); }

__global__ __launch_bounds__(64)
void kv2_kernel(const float* __restrict__ kv, float* __restrict__ kv2,
                const float* __restrict__ wn, const float* __restrict__ bn,
                const float* __restrict__ wm, const float* __restrict__ bm,
                const float* __restrict__ bth)
{
    long r = blockIdx.x;
    int d = threadIdx.x;
    __shared__ float kr[64];
    __shared__ float tmp[64];

    kr[d] = kv[r * 64 + d];
    __syncthreads();

    float thresh = sigmoidf_(g_tsum * (1.f / 512.f) + bth[0]);

    float sn = bn[d], sm = bm[d];
#pragma unroll 8
    for (int e = 0; e < 64; e++) {
        float ke = kr[e];
        sn += ke * wn[d * 64 + e];
        sm += ke * wm[d * 64 + e];
    }
    float denoise = sigmoidf_(sn);
    float mval    = sigmoidf_(sm);
    float mbin    = (mval > thresh) ? 1.f : 0.f;
    float val     = kr[d] * mbin + denoise;

    tmp[d] = val; __syncthreads();
    float mx = -3.4e38f;
    for (int e = 0; e < 64; e++) mx = fmaxf(mx, tmp[e]);
    __syncthreads();
    float ev = expf(val - mx);
    tmp[d] = ev; __syncthreads();
    float sum = 0.f;
    for (int e = 0; e < 64; e++) sum += tmp[e];
    kv2[r * 64 + d] = ev / sum;
}

// ===========================================================================
extern "C" void kernel_launch(void* const* d_in, const int* in_sizes, int n_in,
                              void* d_out, int out_size)
{
    const float* x        = (const float*)d_in[0];
    const float* w_qkv    = (const float*)d_in[1];
    const float* agent    = (const float*)d_in[2];
    const float* w_noise  = (const float*)d_in[3];
    const float* b_noise  = (const float*)d_in[4];
    const float* w_mask   = (const float*)d_in[5];
    const float* b_mask   = (const float*)d_in[6];
    const float* w_thresh = (const float*)d_in[7];
    const float* b_thresh = (const float*)d_in[8];
    float* out = (float*)d_out;

    float *qkv, *big, *kv, *kv2;
    __nv_bfloat16 *xh, *xl, *wh, *wl;
    cudaGetSymbolAddress((void**)&qkv, g_qkv);
    cudaGetSymbolAddress((void**)&big, g_big);
    cudaGetSymbolAddress((void**)&kv,  g_kv);
    cudaGetSymbolAddress((void**)&kv2, g_kv2);
    cudaGetSymbolAddress((void**)&xh,  g_xh);
    cudaGetSymbolAddress((void**)&xl,  g_xl);
    cudaGetSymbolAddress((void**)&wh,  g_wh);
    cudaGetSymbolAddress((void**)&wl,  g_wl);

    cudaFuncSetAttribute(k1_mma_kernel,
                         cudaFuncAttributeMaxDynamicSharedMemorySize, K1_SMEM);

    init_kernel<<<256, 256>>>();

    // 0) bf16 hi/lo split of x and w_qkv
    split_bf16<<<1024, 256>>>(x, xh, xl, 16384L * 512);
    split_bf16<<<256, 256>>>(w_qkv, wh, wl, 1536L * 512);

    // 1) qkv = x @ w_qkv^T via bf16x3 mma.sync : [16384,1536], K=512
    k1_mma_kernel<<<dim3(12, 128), 256, K1_SMEM>>>(xh, xl, wh, wl, qkv);

    // 2) S2[z] = agent[h] @ k[b,h]^T : [256,8192], K=64
    gemm_kernel<true, false><<<dim3(128, 2, 16), 256>>>(
        agent, 64, 0, 16384,
        qkv + 512, 1536, 12582912L, 64,
        big, 8192, 16777216L, 2097152L,
        256, 8192, 64, 1, 1.f);

    // 3) softmax over n
    softmax_rows8192<<<4096, 256>>>(big);

    // 4) kv[z] = S2[z] @ v[b,h] : [256,64], K=8192, split-K=32
    gemm_kernel<false, true><<<dim3(1, 64, 16), 256>>>(
        big, 8192, 16777216L, 2097152L,
        qkv + 1024, 1536, 12582912L, 64,
        kv, 64, 131072L, 16384L,
        256, 64, 8192, 32, 1.f);

    // 5) threshold scalar
    thresh_kernel<<<512, 256>>>(kv, w_thresh);

    // 6) mask/denoise + second softmax -> kv2
    kv2_kernel<<<4096, 64>>>(kv, kv2, w_noise, b_noise, w_mask, b_mask, b_thresh);

    // 7) qa_logits[z] = q[b,h] @ agent[h]^T * 1/8 : [8192,256], K=64
    gemm_kernel<true, false><<<dim3(4, 64, 16), 256>>>(
        qkv, 1536, 12582912L, 64,
        agent, 64, 0, 16384,
        big, 256, 16777216L, 2097152L,
        8192, 256, 64, 1, 0.125f);

    // 8) softmax over a
    softmax_rows256<<<16384, 256>>>(big);

    // 9) out = qa[z] @ kv2[z] : [8192,64], K=256
    gemm_kernel<false, false><<<dim3(1, 64, 16), 256>>>(
        big, 256, 16777216L, 2097152L,
        kv2, 64, 131072L, 16384L,
        out, 512, 4194304L, 64,
        8192, 64, 256, 1, 1.f);
}

// round 10
// speedup vs baseline: 2.0666x; 1.4356x over previous
#include <cuda_runtime.h>
#include <cuda_bf16.h>
#include <math.h>
#include <cstdint>

// Problem constants: B=2, N=8192, DIM=512, H=8, A=256, D=64
__device__ float g_qkv[16384 * 1536];        // qkv scratch (fp32)
__device__ float g_kv [16 * 256 * 64];       // fused num -> normalized kv
__device__ float g_ksum[16 * 256];           // softmax denominators
__device__ float g_tsum;
// bf16 hi/lo split buffers for the big GEMM
__device__ __align__(16) __nv_bfloat16 g_xh[16384 * 512];
__device__ __align__(16) __nv_bfloat16 g_xl[16384 * 512];
__device__ __align__(16) __nv_bfloat16 g_wh[1536 * 512];
__device__ __align__(16) __nv_bfloat16 g_wl[1536 * 512];
// kv2 transposed [bh][d][a], bf16 hi/lo
__device__ __align__(16) __nv_bfloat16 g_kt_h[16 * 64 * 256];
__device__ __align__(16) __nv_bfloat16 g_kt_l[16 * 64 * 256];

// ===========================================================================
// PTX helpers
// ===========================================================================
__device__ __forceinline__ uint32_t smem_to_u32(const void* p) {
    uint32_t a;
    asm("{ .reg .u64 t; cvta.to.shared.u64 t, %1; cvt.u32.u64 %0, t; }" : "=r"(a) : "l"(p));
    return a;
}
#define LDMATRIX_X4(r0, r1, r2, r3, addr) \
    asm volatile("ldmatrix.sync.aligned.m8n8.x4.shared.b16 {%0,%1,%2,%3}, [%4];" \
                 : "=r"(r0), "=r"(r1), "=r"(r2), "=r"(r3) : "r"(addr))
#define LDMATRIX_X4_T(r0, r1, r2, r3, addr) \
    asm volatile("ldmatrix.sync.aligned.m8n8.x4.trans.shared.b16 {%0,%1,%2,%3}, [%4];" \
                 : "=r"(r0), "=r"(r1), "=r"(r2), "=r"(r3) : "r"(addr))
#define MMA_BF16(c, a, b) \
    asm volatile("mma.sync.aligned.m16n8k16.row.col.f32.bf16.bf16.f32 " \
                 "{%0,%1,%2,%3}, {%4,%5,%6,%7}, {%8,%9}, {%0,%1,%2,%3};" \
                 : "+f"((c)[0]), "+f"((c)[1]), "+f"((c)[2]), "+f"((c)[3]) \
                 : "r"((a)[0]), "r"((a)[1]), "r"((a)[2]), "r"((a)[3]), \
                   "r"((b)[0]), "r"((b)[1]))
#define CP_ASYNC16(dst, src) \
    asm volatile("cp.async.cg.shared.global [%0], [%1], 16;" :: "r"(dst), "l"(src))
#define CP_COMMIT() asm volatile("cp.async.commit_group;" ::: "memory")
#define CP_WAIT0()  asm volatile("cp.async.wait_group 0;" ::: "memory")

// pack two floats -> bf16x2 hi word and residual lo word
__device__ __forceinline__ void split2(float a, float b, uint32_t& h, uint32_t& l) {
    __nv_bfloat16 ha = __float2bfloat16_rn(a), hb = __float2bfloat16_rn(b);
    __nv_bfloat162 hp; hp.x = ha; hp.y = hb;
    __nv_bfloat162 lp;
    lp.x = __float2bfloat16_rn(a - __bfloat162float(ha));
    lp.y = __float2bfloat16_rn(b - __bfloat162float(hb));
    h = *(uint32_t*)&hp; l = *(uint32_t*)&lp;
}

// ===========================================================================
// bf16 split kernel (for k1 inputs)
// ===========================================================================
__global__ __launch_bounds__(256)
void split_bf16(const float* __restrict__ in, __nv_bfloat16* __restrict__ hi,
                __nv_bfloat16* __restrict__ lo, long n) {
    for (long i = ((long)blockIdx.x * blockDim.x + threadIdx.x) * 4; i < n;
         i += (long)gridDim.x * blockDim.x * 4) {
        float4 v = *(const float4*)(in + i);
        uint32_t h01, h23, l01, l23;
        split2(v.x, v.y, h01, l01);
        split2(v.z, v.w, h23, l23);
        *(uint2*)(hi + i) = make_uint2(h01, h23);
        *(uint2*)(lo + i) = make_uint2(l01, l23);
    }
}

// ===========================================================================
// K1: C[16384,1536] = X[16384,512] @ W[1536,512]^T via bf16x3 mma.sync.
// (unchanged from the verified round-6 version)
// ===========================================================================
static constexpr int K1_ROWB = 80;
static constexpr int K1_BUF  = 128 * K1_ROWB;
static constexpr int K1_STAGE = 4 * K1_BUF;
static constexpr int K1_SMEM  = 2 * K1_STAGE;

__global__ __launch_bounds__(256)
void k1_mma_kernel(const __nv_bfloat16* __restrict__ xh,
                   const __nv_bfloat16* __restrict__ xl,
                   const __nv_bfloat16* __restrict__ wh,
                   const __nv_bfloat16* __restrict__ wl,
                   float* __restrict__ C)
{
    extern __shared__ char smem[];
    uint32_t sb = smem_to_u32(smem);
    int tid = threadIdx.x;
    int lane = tid & 31, wid = tid >> 5;
    int mw = wid & 1, nw = wid >> 1;
    int nt = blockIdx.x, mt = blockIdx.y;

    const __nv_bfloat16* srcA_h = xh + (long)(mt * 128) * 512;
    const __nv_bfloat16* srcA_l = xl + (long)(mt * 128) * 512;
    const __nv_bfloat16* srcB_h = wh + (long)(nt * 128) * 512;
    const __nv_bfloat16* srcB_l = wl + (long)(nt * 128) * 512;

    float acc[4][4][4];
#pragma unroll
    for (int i = 0; i < 4; i++)
#pragma unroll
        for (int j = 0; j < 4; j++)
#pragma unroll
            for (int q = 0; q < 4; q++) acc[i][j][q] = 0.f;

    int a_tile = lane >> 3, a_rin = lane & 7;
    int a_row = a_rin + (a_tile & 1) * 8;
    int a_kb  = (a_tile >> 1) * 16;
    int b_row = (a_tile >> 1) * 8 + a_rin;
    int b_kb  = (a_tile & 1) * 16;

    auto issue_loads = [&](int stage, int k0) {
        uint32_t base = sb + stage * K1_STAGE;
#pragma unroll
        for (int j = 0; j < 8; j++) {
            int idx = tid + j * 256;
            int buf = idx >> 9;
            int r   = (idx >> 2) & 127;
            int g   = idx & 3;
            const __nv_bfloat16* src =
                (buf == 0 ? srcA_h : buf == 1 ? srcA_l : buf == 2 ? srcB_h : srcB_l)
                + (long)r * 512 + k0 + g * 8;
            uint32_t dst = base + buf * K1_BUF + r * K1_ROWB + g * 16;
            CP_ASYNC16(dst, src);
        }
    };

    issue_loads(0, 0);
    CP_COMMIT(); CP_WAIT0();
    __syncthreads();

    for (int kc = 0; kc < 16; ++kc) {
        int cur = kc & 1;
        if (kc < 15) { issue_loads(cur ^ 1, (kc + 1) * 32); CP_COMMIT(); }

        uint32_t st = sb + cur * K1_STAGE;
        uint32_t Ah = st,              Al = st + K1_BUF;
        uint32_t Bh = st + 2 * K1_BUF, Bl = st + 3 * K1_BUF;

#pragma unroll
        for (int s = 0; s < 2; ++s) {
            int skb = s * 32;
            uint32_t ah[4][4], al[4][4], bh[4][2], bl[4][2];
#pragma unroll
            for (int mf = 0; mf < 4; mf++) {
                uint32_t addr = Ah + (mw * 64 + mf * 16 + a_row) * K1_ROWB + skb + a_kb;
                LDMATRIX_X4(ah[mf][0], ah[mf][1], ah[mf][2], ah[mf][3], addr);
            }
#pragma unroll
            for (int p = 0; p < 2; p++) {
                uint32_t addr = Bh + (nw * 32 + p * 16 + b_row) * K1_ROWB + skb + b_kb;
                LDMATRIX_X4(bh[p * 2][0], bh[p * 2][1], bh[p * 2 + 1][0], bh[p * 2 + 1][1], addr);
                uint32_t addr2 = Bl + (nw * 32 + p * 16 + b_row) * K1_ROWB + skb + b_kb;
                LDMATRIX_X4(bl[p * 2][0], bl[p * 2][1], bl[p * 2 + 1][0], bl[p * 2 + 1][1], addr2);
            }
#pragma unroll
            for (int mf = 0; mf < 4; mf++)
#pragma unroll
                for (int nf = 0; nf < 4; nf++) MMA_BF16(acc[mf][nf], ah[mf], bh[nf]);
#pragma unroll
            for (int mf = 0; mf < 4; mf++)
#pragma unroll
                for (int nf = 0; nf < 4; nf++) MMA_BF16(acc[mf][nf], ah[mf], bl[nf]);
#pragma unroll
            for (int mf = 0; mf < 4; mf++) {
                uint32_t addr = Al + (mw * 64 + mf * 16 + a_row) * K1_ROWB + skb + a_kb;
                LDMATRIX_X4(al[mf][0], al[mf][1], al[mf][2], al[mf][3], addr);
            }
#pragma unroll
            for (int mf = 0; mf < 4; mf++)
#pragma unroll
                for (int nf = 0; nf < 4; nf++) MMA_BF16(acc[mf][nf], al[mf], bh[nf]);
        }

        if (kc < 15) CP_WAIT0();
        __syncthreads();
    }

    int rbase = mt * 128 + mw * 64 + (lane >> 2);
    int cbase = nt * 128 + nw * 32 + (lane & 3) * 2;
#pragma unroll
    for (int mf = 0; mf < 4; mf++)
#pragma unroll
        for (int nf = 0; nf < 4; nf++) {
            long r0 = rbase + mf * 16;
            long cc = cbase + nf * 8;
            *(float2*)(C + r0 * 1536 + cc)       = make_float2(acc[mf][nf][0], acc[mf][nf][1]);
            *(float2*)(C + (r0 + 8) * 1536 + cc) = make_float2(acc[mf][nf][2], acc[mf][nf][3]);
        }
}

// ===========================================================================
// init: zero atomic accumulators
// ===========================================================================
__global__ void init_kernel() {
    int i = blockIdx.x * blockDim.x + threadIdx.x;
    if (i == 0) g_tsum = 0.f;
    if (i < 16 * 256) g_ksum[i] = 0.f;
    for (; i < 16 * 256 * 64; i += gridDim.x * blockDim.x) g_kv[i] = 0.f;
}

// ===========================================================================
// Fused stage A: kv-partials.
//   per (split, bh): S = agent[h] @ K^T (bf16x3), P = exp(S) (no max-sub),
//   num += P @ V, den += rowsum(P). Atomic accumulate into g_kv / g_ksum.
// grid (8, 16), 256 threads (8 warps x 32 agents).
// ===========================================================================
static constexpr int A_STR   = 144;
static constexpr int A_AGL   = 36864;    // agent lo offset
static constexpr int A_KH    = 73728;    // K/V tiles base
static constexpr int A_KL    = A_KH + 4608;
static constexpr int A_VH    = A_KH + 9216;
static constexpr int A_VL    = A_KH + 13824;
static constexpr int A_SMEM  = 92160;

__global__ __launch_bounds__(256)
void attn_kv_kernel(const float* __restrict__ qkv, const float* __restrict__ agent,
                    float* __restrict__ kv, float* __restrict__ ksum)
{
    extern __shared__ char smem[];
    char* sc = smem;
    uint32_t sb = smem_to_u32(smem);
    int tid = threadIdx.x, lane = tid & 31, wid = tid >> 5;
    int split = blockIdx.x, bh = blockIdx.y;
    int b = bh >> 3, h = bh & 7;
    int t8 = lane >> 3, rin = lane & 7;
    int a_row = rin + (t8 & 1) * 8, a_kb = (t8 >> 1) * 16;   // A-frag pattern
    int b_row = (t8 >> 1) * 8 + rin, b_kb = (t8 & 1) * 16;   // B-frag pattern
    int v_row = (t8 & 1) * 8 + rin, v_cb = (t8 >> 1) * 16;   // B-frag trans

    // ---- stage agent[h] -> hi/lo smem (resident)
    const float* ag = agent + h * 16384;
    for (int i = tid; i < 4096; i += 256) {
        int r = i >> 4, c4 = i & 15;
        float4 v = *(const float4*)(ag + r * 64 + c4 * 4);
        uint32_t h01, h23, l01, l23;
        split2(v.x, v.y, h01, l01); split2(v.z, v.w, h23, l23);
        *(uint2*)(sc + r * A_STR + c4 * 8)         = make_uint2(h01, h23);
        *(uint2*)(sc + A_AGL + r * A_STR + c4 * 8) = make_uint2(l01, l23);
    }

    float kvacc[2][8][4];
#pragma unroll
    for (int i = 0; i < 2; i++)
#pragma unroll
        for (int j = 0; j < 8; j++)
#pragma unroll
            for (int q = 0; q < 4; q++) kvacc[i][j][q] = 0.f;
    float rs[2][2] = {{0.f, 0.f}, {0.f, 0.f}};

    const float* kbase = qkv + 512 + h * 64 + (long)(b * 8192 + split * 1024) * 1536;
    int lr = tid >> 3, lc = tid & 7;

    // register prefetch of tile 0
    float4 pk0, pk1, pv0, pv1;
    {
        const float* kr = kbase + (long)lr * 1536 + lc * 8;
        pk0 = *(const float4*)kr;       pk1 = *(const float4*)(kr + 4);
        pv0 = *(const float4*)(kr + 512); pv1 = *(const float4*)(kr + 516);
    }
    __syncthreads();   // agent staged

    for (int t = 0; t < 32; ++t) {
        // store prefetched tile (hi/lo split)
        {
            uint32_t x0, x1, x2, x3, y0, y1, y2, y3;
            split2(pk0.x, pk0.y, x0, y0); split2(pk0.z, pk0.w, x1, y1);
            split2(pk1.x, pk1.y, x2, y2); split2(pk1.z, pk1.w, x3, y3);
            *(uint4*)(sc + A_KH + lr * A_STR + lc * 16) = make_uint4(x0, x1, x2, x3);
            *(uint4*)(sc + A_KL + lr * A_STR + lc * 16) = make_uint4(y0, y1, y2, y3);
            split2(pv0.x, pv0.y, x0, y0); split2(pv0.z, pv0.w, x1, y1);
            split2(pv1.x, pv1.y, x2, y2); split2(pv1.z, pv1.w, x3, y3);
            *(uint4*)(sc + A_VH + lr * A_STR + lc * 16) = make_uint4(x0, x1, x2, x3);
            *(uint4*)(sc + A_VL + lr * A_STR + lc * 16) = make_uint4(y0, y1, y2, y3);
        }
        __syncthreads();
        if (t < 31) {
            const float* kr = kbase + (long)((t + 1) * 32 + lr) * 1536 + lc * 8;
            pk0 = *(const float4*)kr;         pk1 = *(const float4*)(kr + 4);
            pv0 = *(const float4*)(kr + 512); pv1 = *(const float4*)(kr + 516);
        }

        // ---- S = agent @ K^T  [32 agents x 32 tok], bf16x3
        float s[2][4][4];
#pragma unroll
        for (int i = 0; i < 2; i++)
#pragma unroll
            for (int j = 0; j < 4; j++)
#pragma unroll
                for (int q = 0; q < 4; q++) s[i][j][q] = 0.f;

#pragma unroll
        for (int kf = 0; kf < 4; ++kf) {
            uint32_t ah[2][4], al[2][4];
#pragma unroll
            for (int mf = 0; mf < 2; ++mf) {
                uint32_t ad = sb + (wid * 32 + mf * 16 + a_row) * A_STR + kf * 32 + a_kb;
                LDMATRIX_X4(ah[mf][0], ah[mf][1], ah[mf][2], ah[mf][3], ad);
                LDMATRIX_X4(al[mf][0], al[mf][1], al[mf][2], al[mf][3], ad + A_AGL);
            }
            uint32_t kbh[4][2], kbl[4][2];
#pragma unroll
            for (int p = 0; p < 2; ++p) {
                uint32_t ad = sb + A_KH + (p * 16 + b_row) * A_STR + kf * 32 + b_kb;
                LDMATRIX_X4(kbh[p * 2][0], kbh[p * 2][1], kbh[p * 2 + 1][0], kbh[p * 2 + 1][1], ad);
                LDMATRIX_X4(kbl[p * 2][0], kbl[p * 2][1], kbl[p * 2 + 1][0], kbl[p * 2 + 1][1], ad + 4608);
            }
#pragma unroll
            for (int mf = 0; mf < 2; ++mf)
#pragma unroll
                for (int nf = 0; nf < 4; ++nf) {
                    MMA_BF16(s[mf][nf], ah[mf], kbh[nf]);
                    MMA_BF16(s[mf][nf], ah[mf], kbl[nf]);
                    MMA_BF16(s[mf][nf], al[mf], kbh[nf]);
                }
        }

        // ---- P = exp(S), rowsums, pack A-frags for PV
        uint32_t ph[2][2][4], pl[2][2][4];
#pragma unroll
        for (int mf = 0; mf < 2; ++mf) {
#pragma unroll
            for (int nf = 0; nf < 4; ++nf) {
                s[mf][nf][0] = expf(s[mf][nf][0]);
                s[mf][nf][1] = expf(s[mf][nf][1]);
                s[mf][nf][2] = expf(s[mf][nf][2]);
                s[mf][nf][3] = expf(s[mf][nf][3]);
                rs[mf][0] += s[mf][nf][0] + s[mf][nf][1];
                rs[mf][1] += s[mf][nf][2] + s[mf][nf][3];
            }
#pragma unroll
            for (int kt = 0; kt < 2; ++kt) {
                split2(s[mf][2 * kt][0],     s[mf][2 * kt][1],     ph[mf][kt][0], pl[mf][kt][0]);
                split2(s[mf][2 * kt][2],     s[mf][2 * kt][3],     ph[mf][kt][1], pl[mf][kt][1]);
                split2(s[mf][2 * kt + 1][0], s[mf][2 * kt + 1][1], ph[mf][kt][2], pl[mf][kt][2]);
                split2(s[mf][2 * kt + 1][2], s[mf][2 * kt + 1][3], ph[mf][kt][3], pl[mf][kt][3]);
            }
        }

        // ---- kvacc += P @ V  (V^T via trans ldmatrix), bf16x3
#pragma unroll
        for (int kt = 0; kt < 2; ++kt) {
#pragma unroll
            for (int p = 0; p < 4; ++p) {
                uint32_t bvh[2][2], bvl[2][2];
                uint32_t ad = sb + A_VH + (kt * 16 + v_row) * A_STR + p * 32 + v_cb;
                LDMATRIX_X4_T(bvh[0][0], bvh[0][1], bvh[1][0], bvh[1][1], ad);
                LDMATRIX_X4_T(bvl[0][0], bvl[0][1], bvl[1][0], bvl[1][1], ad + 4608);
#pragma unroll
                for (int mf = 0; mf < 2; ++mf)
#pragma unroll
                    for (int j = 0; j < 2; ++j) {
                        int nf = p * 2 + j;
                        MMA_BF16(kvacc[mf][nf], ph[mf][kt], bvh[j]);
                        MMA_BF16(kvacc[mf][nf], ph[mf][kt], bvl[j]);
                        MMA_BF16(kvacc[mf][nf], pl[mf][kt], bvh[j]);
                    }
            }
        }
        __syncthreads();
    }

    // ---- reduce row sums (lanes l, l^1, l^2 share a row) + atomics
#pragma unroll
    for (int mf = 0; mf < 2; ++mf)
#pragma unroll
        for (int j = 0; j < 2; ++j) {
            float r = rs[mf][j];
            r += __shfl_xor_sync(0xffffffffu, r, 1);
            r += __shfl_xor_sync(0xffffffffu, r, 2);
            if ((lane & 3) == 0)
                atomicAdd(&ksum[bh * 256 + wid * 32 + mf * 16 + j * 8 + (lane >> 2)], r);
        }
    float* kvb = kv + bh * 16384;
#pragma unroll
    for (int mf = 0; mf < 2; ++mf)
#pragma unroll
        for (int nf = 0; nf < 8; ++nf) {
            int r0 = wid * 32 + mf * 16 + (lane >> 2);
            int c  = nf * 8 + (lane & 3) * 2;
            atomicAdd(&kvb[r0 * 64 + c],           kvacc[mf][nf][0]);
            atomicAdd(&kvb[r0 * 64 + c + 1],       kvacc[mf][nf][1]);
            atomicAdd(&kvb[(r0 + 8) * 64 + c],     kvacc[mf][nf][2]);
            atomicAdd(&kvb[(r0 + 8) * 64 + c + 1], kvacc[mf][nf][3]);
        }
}

// kv /= ksum
__global__ __launch_bounds__(256)
void kv_div_kernel(float* __restrict__ kv, const float* __restrict__ ksum) {
    int i = blockIdx.x * 256 + threadIdx.x;
    kv[i] = kv[i] / ksum[i >> 6];
}

// thresh: tsum = sum_i kv_flat[i] * w_thresh[i % 512]  (row-major reshape)
__global__ __launch_bounds__(256)
void thresh_kernel(const float* __restrict__ kv, const float* __restrict__ wth)
{
    __shared__ float red[256];
    float s = 0.f;
    for (long i = blockIdx.x * 256 + threadIdx.x; i < 16L * 256 * 64;
         i += (long)gridDim.x * 256) {
        s += kv[i] * wth[i & 511];
    }
    red[threadIdx.x] = s; __syncthreads();
    for (int st = 128; st > 0; st >>= 1) {
        if (threadIdx.x < st) red[threadIdx.x] += red[threadIdx.x + st];
        __syncthreads();
    }
    if (threadIdx.x == 0) atomicAdd(&g_tsum, red[0]);
}

__device__ __forceinline__ float sigmoidf_(float x) { return 1.f / (1.f + expf(-x)); }

// ===========================================================================
// kv2 = softmax_d(kv * mask + denoise); write TRANSPOSED bf16 hi/lo [bh][d][a]
// ===========================================================================
__global__ __launch_bounds__(64)
void kv2_kernel(const float* __restrict__ kv,
                __nv_bfloat16* __restrict__ kth, __nv_bfloat16* __restrict__ ktl,
                const float* __restrict__ wn, const float* __restrict__ bn,
                const float* __restrict__ wm, const float* __restrict__ bm,
                const float* __restrict__ bth)
{
    long r = blockIdx.x;               // bh*256 + a
    int bh = (int)(r >> 8), a = (int)(r & 255);
    int d = threadIdx.x;
    __shared__ float kr[64];
    __shared__ float tmp[64];

    kr[d] = kv[r * 64 + d];
    __syncthreads();

    float thresh = sigmoidf_(g_tsum * (1.f / 512.f) + bth[0]);

    float sn = bn[d], sm = bm[d];
#pragma unroll 8
    for (int e = 0; e < 64; e++) {
        float ke = kr[e];
        sn += ke * wn[d * 64 + e];
        sm += ke * wm[d * 64 + e];
    }
    float denoise = sigmoidf_(sn);
    float mval    = sigmoidf_(sm);
    float mbin    = (mval > thresh) ? 1.f : 0.f;
    float val     = kr[d] * mbin + denoise;

    tmp[d] = val; __syncthreads();
    float mx = -3.4e38f;
    for (int e = 0; e < 64; e++) mx = fmaxf(mx, tmp[e]);
    __syncthreads();
    float ev = expf(val - mx);
    tmp[d] = ev; __syncthreads();
    float sum = 0.f;
    for (int e = 0; e < 64; e++) sum += tmp[e];
    float v = ev / sum;
    __nv_bfloat16 hh = __float2bfloat16_rn(v);
    kth[bh * 16384 + d * 256 + a] = hh;
    ktl[bh * 16384 + d * 256 + a] = __float2bfloat16_rn(v - __bfloat162float(hh));
}

// ===========================================================================
// Fused stage B: out tile.
//   per (qtile, bh): L = (q*0.125) @ agent^T (bf16x3); P = exp(L);
//   O = P @ kv2^T (bf16x3, kv2 pre-transposed); out = O / rowsum(P).
// grid (128, 16), 256 threads; warps: mw=wid&1 (32 rows), nw=wid>>2.. (64 agents)
// ===========================================================================
static constexpr int B_STR  = 144;
static constexpr int B_QL   = 9216;
static constexpr int B_AG   = 18432;
static constexpr int B_AGL  = 36864;   // relative to B_AG
static constexpr int B_KT   = 92160;
static constexpr int B_KTL  = 33792;   // relative to B_KT
static constexpr int B_RS   = 159744;
static constexpr int B_SMEM = 160768;
static constexpr int KT_STR = 528;

__global__ __launch_bounds__(256)
void attn_out_kernel(const float* __restrict__ qkv, const float* __restrict__ agent,
                     const __nv_bfloat16* __restrict__ kth,
                     const __nv_bfloat16* __restrict__ ktl,
                     float* __restrict__ out)
{
    extern __shared__ char smem[];
    char* sc = smem;
    uint32_t sb = smem_to_u32(smem);
    int tid = threadIdx.x, lane = tid & 31, wid = tid >> 5;
    int qt = blockIdx.x, bh = blockIdx.y;
    int b = bh >> 3, h = bh & 7;
    int mw = wid & 1, nw = wid >> 1;
    int t8 = lane >> 3, rin = lane & 7;
    int a_row = rin + (t8 & 1) * 8, a_kb = (t8 >> 1) * 16;
    int b_row = (t8 >> 1) * 8 + rin, b_kb = (t8 & 1) * 16;

    // ---- loads: Q tile (scaled 0.125), agent, kv2t
    {
        const float* qb = qkv + h * 64 + (long)(b * 8192 + qt * 64) * 1536;
        int lr = tid >> 2, lc = tid & 3;
#pragma unroll
        for (int g = 0; g < 4; ++g) {
            float4 v = *(const float4*)(qb + (long)lr * 1536 + lc * 16 + g * 4);
            v.x *= 0.125f; v.y *= 0.125f; v.z *= 0.125f; v.w *= 0.125f;
            uint32_t h01, h23, l01, l23;
            split2(v.x, v.y, h01, l01); split2(v.z, v.w, h23, l23);
            *(uint2*)(sc + lr * B_STR + lc * 32 + g * 8)        = make_uint2(h01, h23);
            *(uint2*)(sc + B_QL + lr * B_STR + lc * 32 + g * 8) = make_uint2(l01, l23);
        }
    }
    {
        const float* ag = agent + h * 16384;
        for (int i = tid; i < 4096; i += 256) {
            int r = i >> 4, c4 = i & 15;
            float4 v = *(const float4*)(ag + r * 64 + c4 * 4);
            uint32_t h01, h23, l01, l23;
            split2(v.x, v.y, h01, l01); split2(v.z, v.w, h23, l23);
            *(uint2*)(sc + B_AG + r * B_STR + c4 * 8)         = make_uint2(h01, h23);
            *(uint2*)(sc + B_AG + B_AGL + r * B_STR + c4 * 8) = make_uint2(l01, l23);
        }
    }
    for (int c = tid; c < 2048; c += 256) {
        int r = c >> 5, c16 = c & 31;
        CP_ASYNC16(sb + B_KT + r * KT_STR + c16 * 16,         kth + bh * 16384 + r * 256 + c16 * 8);
        CP_ASYNC16(sb + B_KT + B_KTL + r * KT_STR + c16 * 16, ktl + bh * 16384 + r * 256 + c16 * 8);
    }
    CP_COMMIT(); CP_WAIT0();
    __syncthreads();

    // ---- S = Q @ agent^T  [32 rows x 64 agents], bf16x3
    float s[2][8][4];
#pragma unroll
    for (int i = 0; i < 2; i++)
#pragma unroll
        for (int j = 0; j < 8; j++)
#pragma unroll
            for (int q = 0; q < 4; q++) s[i][j][q] = 0.f;

#pragma unroll
    for (int kf = 0; kf < 4; ++kf) {
        uint32_t ah[2][4], al[2][4];
#pragma unroll
        for (int mf = 0; mf < 2; ++mf) {
            uint32_t ad = sb + (mw * 32 + mf * 16 + a_row) * B_STR + kf * 32 + a_kb;
            LDMATRIX_X4(ah[mf][0], ah[mf][1], ah[mf][2], ah[mf][3], ad);
            LDMATRIX_X4(al[mf][0], al[mf][1], al[mf][2], al[mf][3], ad + B_QL);
        }
#pragma unroll
        for (int p = 0; p < 4; ++p) {
            uint32_t bhf[2][2], blf[2][2];
            uint32_t ad = sb + B_AG + (nw * 64 + p * 16 + b_row) * B_STR + kf * 32 + b_kb;
            LDMATRIX_X4(bhf[0][0], bhf[0][1], bhf[1][0], bhf[1][1], ad);
            LDMATRIX_X4(blf[0][0], blf[0][1], blf[1][0], blf[1][1], ad + B_AGL);
#pragma unroll
            for (int mf = 0; mf < 2; ++mf)
#pragma unroll
                for (int j = 0; j < 2; ++j) {
                    int nf = p * 2 + j;
                    MMA_BF16(s[mf][nf], ah[mf], bhf[j]);
                    MMA_BF16(s[mf][nf], ah[mf], blf[j]);
                    MMA_BF16(s[mf][nf], al[mf], bhf[j]);
                }
        }
    }

    // ---- exp, rowsum partials, pack P frags
    float* rsp = (float*)(sc + B_RS);
    uint32_t ph[2][4][4], pl[2][4][4];
#pragma unroll
    for (int mf = 0; mf < 2; ++mf) {
        float r0s = 0.f, r1s = 0.f;
#pragma unroll
        for (int nf = 0; nf < 8; ++nf) {
            s[mf][nf][0] = expf(s[mf][nf][0]);
            s[mf][nf][1] = expf(s[mf][nf][1]);
            s[mf][nf][2] = expf(s[mf][nf][2]);
            s[mf][nf][3] = expf(s[mf][nf][3]);
            r0s += s[mf][nf][0] + s[mf][nf][1];
            r1s += s[mf][nf][2] + s[mf][nf][3];
        }
        r0s += __shfl_xor_sync(0xffffffffu, r0s, 1);
        r0s += __shfl_xor_sync(0xffffffffu, r0s, 2);
        r1s += __shfl_xor_sync(0xffffffffu, r1s, 1);
        r1s += __shfl_xor_sync(0xffffffffu, r1s, 2);
        if ((lane & 3) == 0) {
            rsp[nw * 64 + mw * 32 + mf * 16 + (lane >> 2)]     = r0s;
            rsp[nw * 64 + mw * 32 + mf * 16 + (lane >> 2) + 8] = r1s;
        }
#pragma unroll
        for (int kt = 0; kt < 4; ++kt) {
            split2(s[mf][2 * kt][0],     s[mf][2 * kt][1],     ph[mf][kt][0], pl[mf][kt][0]);
            split2(s[mf][2 * kt][2],     s[mf][2 * kt][3],     ph[mf][kt][1], pl[mf][kt][1]);
            split2(s[mf][2 * kt + 1][0], s[mf][2 * kt + 1][1], ph[mf][kt][2], pl[mf][kt][2]);
            split2(s[mf][2 * kt + 1][2], s[mf][2 * kt + 1][3], ph[mf][kt][3], pl[mf][kt][3]);
        }
    }
    __syncthreads();   // rowsums visible; agent smem free after this point

    // ---- O = P @ kv2t  (k = this warp's 64 agents)
    float o[2][8][4];
#pragma unroll
    for (int i = 0; i < 2; i++)
#pragma unroll
        for (int j = 0; j < 8; j++)
#pragma unroll
            for (int q = 0; q < 4; q++) o[i][j][q] = 0.f;

#pragma unroll
    for (int kt = 0; kt < 4; ++kt) {
#pragma unroll
        for (int p = 0; p < 4; ++p) {
            uint32_t bhf[2][2], blf[2][2];
            uint32_t ad = sb + B_KT + (p * 16 + b_row) * KT_STR + (nw * 64 + kt * 16) * 2 + b_kb;
            LDMATRIX_X4(bhf[0][0], bhf[0][1], bhf[1][0], bhf[1][1], ad);
            LDMATRIX_X4(blf[0][0], blf[0][1], blf[1][0], blf[1][1], ad + B_KTL);
#pragma unroll
            for (int mf = 0; mf < 2; ++mf)
#pragma unroll
                for (int j = 0; j < 2; ++j) {
                    int nf = p * 2 + j;
                    MMA_BF16(o[mf][nf], ph[mf][kt], bhf[j]);
                    MMA_BF16(o[mf][nf], ph[mf][kt], blf[j]);
                    MMA_BF16(o[mf][nf], pl[mf][kt], bhf[j]);
                }
        }
    }

    // ---- cross-warp-column reduction of O partials (reuse agent smem area)
    if (nw > 0) {
        char* pp = sc + B_AG + (nw - 1) * 16384;
#pragma unroll
        for (int mf = 0; mf < 2; ++mf)
#pragma unroll
            for (int nf = 0; nf < 8; ++nf) {
                int r0 = mw * 32 + mf * 16 + (lane >> 2);
                int c  = nf * 8 + (lane & 3) * 2;
                *(float2*)(pp + (r0 * 64 + c) * 4)       = make_float2(o[mf][nf][0], o[mf][nf][1]);
                *(float2*)(pp + ((r0 + 8) * 64 + c) * 4) = make_float2(o[mf][nf][2], o[mf][nf][3]);
            }
    }
    __syncthreads();

    if (nw == 0) {
#pragma unroll
        for (int mf = 0; mf < 2; ++mf) {
            int r0 = mw * 32 + mf * 16 + (lane >> 2);
            float inv0 = 1.f / (rsp[r0] + rsp[64 + r0] + rsp[128 + r0] + rsp[192 + r0]);
            float inv1 = 1.f / (rsp[r0 + 8] + rsp[64 + r0 + 8] + rsp[128 + r0 + 8] + rsp[192 + r0 + 8]);
#pragma unroll
            for (int nf = 0; nf < 8; ++nf) {
                int c = nf * 8 + (lane & 3) * 2;
                float v0 = o[mf][nf][0], v1 = o[mf][nf][1];
                float v2 = o[mf][nf][2], v3 = o[mf][nf][3];
#pragma unroll
                for (int i = 0; i < 3; ++i) {
                    char* pp = sc + B_AG + i * 16384;
                    float2 a0 = *(float2*)(pp + (r0 * 64 + c) * 4);
                    float2 a1 = *(float2*)(pp + ((r0 + 8) * 64 + c) * 4);
                    v0 += a0.x; v1 += a0.y; v2 += a1.x; v3 += a1.y;
                }
                long gr = (long)(b * 8192 + qt * 64 + r0) * 512 + h * 64 + c;
                *(float2*)(out + gr)             = make_float2(v0 * inv0, v1 * inv0);
                *(float2*)(out + gr + 8 * 512)   = make_float2(v2 * inv1, v3 * inv1);
            }
        }
    }
}

// ===========================================================================
extern "C" void kernel_launch(void* const* d_in, const int* in_sizes, int n_in,
                              void* d_out, int out_size)
{
    const float* x        = (const float*)d_in[0];
    const float* w_qkv    = (const float*)d_in[1];
    const float* agent    = (const float*)d_in[2];
    const float* w_noise  = (const float*)d_in[3];
    const float* b_noise  = (const float*)d_in[4];
    const float* w_mask   = (const float*)d_in[5];
    const float* b_mask   = (const float*)d_in[6];
    const float* w_thresh = (const float*)d_in[7];
    const float* b_thresh = (const float*)d_in[8];
    float* out = (float*)d_out;

    float *qkv, *kv, *ksum;
    __nv_bfloat16 *xh, *xl, *wh, *wl, *kth, *ktl;
    cudaGetSymbolAddress((void**)&qkv, g_qkv);
    cudaGetSymbolAddress((void**)&kv,  g_kv);
    cudaGetSymbolAddress((void**)&ksum, g_ksum);
    cudaGetSymbolAddress((void**)&xh,  g_xh);
    cudaGetSymbolAddress((void**)&xl,  g_xl);
    cudaGetSymbolAddress((void**)&wh,  g_wh);
    cudaGetSymbolAddress((void**)&wl,  g_wl);
    cudaGetSymbolAddress((void**)&kth, g_kt_h);
    cudaGetSymbolAddress((void**)&ktl, g_kt_l);

    cudaFuncSetAttribute(k1_mma_kernel,
                         cudaFuncAttributeMaxDynamicSharedMemorySize, K1_SMEM);
    cudaFuncSetAttribute(attn_kv_kernel,
                         cudaFuncAttributeMaxDynamicSharedMemorySize, A_SMEM);
    cudaFuncSetAttribute(attn_out_kernel,
                         cudaFuncAttributeMaxDynamicSharedMemorySize, B_SMEM);

    init_kernel<<<256, 256>>>();

    // 0) bf16 hi/lo split of x and w_qkv
    split_bf16<<<1024, 256>>>(x, xh, xl, 16384L * 512);
    split_bf16<<<256, 256>>>(w_qkv, wh, wl, 1536L * 512);

    // 1) qkv = x @ w_qkv^T via bf16x3 mma.sync
    k1_mma_kernel<<<dim3(12, 128), 256, K1_SMEM>>>(xh, xl, wh, wl, qkv);

    // 2) fused: ka softmax-partials + kv accumulation
    attn_kv_kernel<<<dim3(8, 16), 256, A_SMEM>>>(qkv, agent, kv, ksum);

    // 3) normalize kv
    kv_div_kernel<<<1024, 256>>>(kv, ksum);

    // 4) threshold scalar
    thresh_kernel<<<512, 256>>>(kv, w_thresh);

    // 5) mask/denoise + second softmax -> kv2 transposed bf16 hi/lo
    kv2_kernel<<<4096, 64>>>(kv, kth, ktl, w_noise, b_noise, w_mask, b_mask, b_thresh);

    // 6) fused: qa softmax + out = qa @ kv2
    attn_out_kernel<<<dim3(128, 16), 256, B_SMEM>>>(qkv, agent, kth, ktl, out);
}